// round 2
// baseline (speedup 1.0000x reference)
#include <cuda_runtime.h>

#define Bb   2
#define QLn  256
#define KLn  256
#define QDn  1024
#define Hn   512
#define C3n  1536
#define EPSf 1e-5f

typedef unsigned long long ull;

// ---------------- device scratch (static, no allocation) ----------------
__device__ __align__(16) float g_WqT[QDn*Hn];     // [d][h] = Wq[h][d]
__device__ __align__(16) float g_WkT[QDn*Hn];
__device__ __align__(16) float g_AuT[Hn*Hn];      // [j][h] = Wu[h, j]      * lnw[j]
__device__ __align__(16) float g_BuT[Hn*Hn];      // [j][h] = Wu[h, H+j]    * lnw[H+j]
__device__ __align__(16) float g_CuT[Hn*Hn];      // [j][h] = Wu[h, 2H+j]   * lnw[2H+j]
__device__ __align__(16) float g_AvT[Hn*Hn];
__device__ __align__(16) float g_BvT[Hn*Hn];
__device__ __align__(16) float g_CvT[Hn*Hn];
__device__ __align__(16) float g_gu[Hn];          // Wu @ ln_w
__device__ __align__(16) float g_cu[Hn];          // Wu @ ln_b + bu
__device__ __align__(16) float g_gv[Hn];
__device__ __align__(16) float g_cv[Hn];
__device__ __align__(16) float g_qproj[Bb*QLn*Hn];
__device__ __align__(16) float g_kproj[Bb*KLn*Hn];
__device__ __align__(16) float g_ruq[Bb*QLn*Hn];  // A_u q
__device__ __align__(16) float g_rvq[Bb*QLn*Hn];  // A_v q
__device__ __align__(16) float g_ruk[Bb*KLn*Hn];  // B_u k
__device__ __align__(16) float g_rvk[Bb*KLn*Hn];  // B_v k

// ---------------- f32x2 packed-fma helpers ----------------
__device__ __forceinline__ ull fma2(ull a, ull b, ull c) {
    ull d;
    asm("fma.rn.f32x2 %0, %1, %2, %3;" : "=l"(d) : "l"(a), "l"(b), "l"(c));
    return d;
}
__device__ __forceinline__ ull pack2(float x) {
    ull d;
    asm("mov.b64 %0, {%1, %1};" : "=l"(d) : "f"(x));
    return d;
}
__device__ __forceinline__ float2 unpack2(ull v) {
    float2 r;
    asm("mov.b64 {%0, %1}, %2;" : "=f"(r.x), "=f"(r.y) : "l"(v));
    return r;
}

// ---------------- prep kernels ----------------
__global__ void prep_transpose(const float* __restrict__ Wq, const float* __restrict__ Wk) {
    int stride = gridDim.x * blockDim.x;
    for (int i = blockIdx.x * blockDim.x + threadIdx.x; i < QDn * Hn; i += stride) {
        int d = i / Hn, h = i - d * Hn;
        g_WqT[i] = Wq[h * QDn + d];
        g_WkT[i] = Wk[h * QDn + d];
    }
}

__global__ void prep_split(const float* __restrict__ Wu, const float* __restrict__ Wv,
                           const float* __restrict__ lnw) {
    int stride = gridDim.x * blockDim.x;
    for (int i = blockIdx.x * blockDim.x + threadIdx.x; i < Hn * Hn; i += stride) {
        int j = i / Hn, h = i - j * Hn;
        float w0 = lnw[j], w1 = lnw[Hn + j], w2 = lnw[2 * Hn + j];
        const float* wu = Wu + h * C3n;
        const float* wv = Wv + h * C3n;
        g_AuT[i] = wu[j] * w0;          g_AvT[i] = wv[j] * w0;
        g_BuT[i] = wu[Hn + j] * w1;     g_BvT[i] = wv[Hn + j] * w1;
        g_CuT[i] = wu[2 * Hn + j] * w2; g_CvT[i] = wv[2 * Hn + j] * w2;
    }
}

__global__ void prep_vec(const float* __restrict__ Wu, const float* __restrict__ bu,
                         const float* __restrict__ Wv, const float* __restrict__ bv,
                         const float* __restrict__ lnw, const float* __restrict__ lnb) {
    int w = (blockIdx.x * blockDim.x + threadIdx.x) >> 5;
    int lane = threadIdx.x & 31;
    if (w >= Hn) return;
    float gu = 0.f, cu = 0.f, gv = 0.f, cv = 0.f;
    for (int c = lane; c < C3n; c += 32) {
        float wl = lnw[c], bl = lnb[c];
        float a = Wu[w * C3n + c], d = Wv[w * C3n + c];
        gu += a * wl; cu += a * bl; gv += d * wl; cv += d * bl;
    }
    #pragma unroll
    for (int o = 16; o; o >>= 1) {
        gu += __shfl_xor_sync(0xffffffffu, gu, o);
        cu += __shfl_xor_sync(0xffffffffu, cu, o);
        gv += __shfl_xor_sync(0xffffffffu, gv, o);
        cv += __shfl_xor_sync(0xffffffffu, cv, o);
    }
    if (lane == 0) {
        g_gu[w] = gu; g_cu[w] = cu + bu[w];
        g_gv[w] = gv; g_cv[w] = cv + bv[w];
    }
}

// ---------------- generic row-major GEMM: C[M,N] = A[M,K] * B[K,N] ----------------
__global__ __launch_bounds__(256) void gemm_rm(const float* __restrict__ A,
                                               const float* __restrict__ Bm,
                                               float* __restrict__ C,
                                               int M, int N, int Kd) {
    __shared__ __align__(16) float As[16][68];  // As[kk][m]
    __shared__ __align__(16) float Bs[16][68];  // Bs[kk][n]
    const int t  = threadIdx.x;
    const int tx = t & 15, ty = t >> 4;
    const int bm = blockIdx.y * 64, bn = blockIdx.x * 64;
    float acc[4][4] = {};
    for (int kb = 0; kb < Kd; kb += 16) {
        #pragma unroll
        for (int l = 0; l < 4; l++) {
            int e = t + l * 256;
            int m = e >> 4, kk = e & 15;
            As[kk][m] = A[(bm + m) * Kd + kb + kk];
            int n = e & 63, k2 = e >> 6;
            Bs[k2][n] = Bm[(kb + k2) * N + bn + n];
        }
        __syncthreads();
        #pragma unroll
        for (int kk = 0; kk < 16; kk++) {
            float4 a = *(const float4*)&As[kk][ty * 4];
            float4 b = *(const float4*)&Bs[kk][tx * 4];
            float aw[4] = {a.x, a.y, a.z, a.w};
            float bw[4] = {b.x, b.y, b.z, b.w};
            #pragma unroll
            for (int i = 0; i < 4; i++)
                #pragma unroll
                for (int j = 0; j < 4; j++)
                    acc[i][j] += aw[i] * bw[j];
        }
        __syncthreads();
    }
    #pragma unroll
    for (int i = 0; i < 4; i++) {
        float4 o = make_float4(acc[i][0], acc[i][1], acc[i][2], acc[i][3]);
        *(float4*)&C[(bm + ty * 4 + i) * N + bn + tx * 4] = o;
    }
}

// ---------------- main fused kernel ----------------
// grid: (KL/128, B*QL); block: 256 threads (tx = h-dir 16, ty = k-dir 16)
// Block computes out[b, q, k0..k0+127] fully: per-pair LN stats + the
// C_u/C_v (q⊙k) contraction (128k x 128h tile, h looped 4x) + gated epilogue.
__global__ __launch_bounds__(256, 1) void gated_main(const float* __restrict__ Wo,
                                                     const float* __restrict__ bo,
                                                     float* __restrict__ out) {
    __shared__ __align__(16) float qrow[Hn];
    __shared__ __align__(16) float KsT[16][132];  // [j][k] scaled K tile
    __shared__ __align__(16) float BuS[16][132];  // [j][h] C_u^T tile
    __shared__ __align__(16) float BvS[16][132];
    __shared__ float muS[128], rsS[128];
    __shared__ float ruqS[128], rvqS[128], guS[128], cuS[128], gvS[128], cvS[128], woS[128];
    __shared__ float sqv[2];

    const int t    = threadIdx.x;
    const int tx   = t & 15;
    const int ty   = t >> 4;
    const int warp = t >> 5;
    const int lane = t & 31;
    const int bq   = blockIdx.y;          // b*QL + q
    const int b    = bq >> 8;
    const int k0   = blockIdx.x * 128;

    const float* qp     = g_qproj + bq * Hn;
    const float* kpbase = g_kproj + (b * KLn + k0) * Hn;

    qrow[t]       = qp[t];
    qrow[t + 256] = qp[t + 256];
    __syncthreads();

    // Sq, Sq2 (warp 0)
    if (warp == 0) {
        float s1 = 0.f, s2 = 0.f;
        #pragma unroll
        for (int j = lane; j < Hn; j += 32) { float v = qrow[j]; s1 += v; s2 += v * v; }
        #pragma unroll
        for (int o = 16; o; o >>= 1) {
            s1 += __shfl_xor_sync(0xffffffffu, s1, o);
            s2 += __shfl_xor_sync(0xffffffffu, s2, o);
        }
        if (lane == 0) { sqv[0] = s1; sqv[1] = s2; }
    }

    // per-k stats: Sk, Sk2, q.k, sum((q_j k_j)^2) — 8 warps x 16 rows
    for (int r = 0; r < 16; r++) {
        int kk = warp * 16 + r;
        const float* kp = kpbase + kk * Hn;
        float sk = 0.f, sk2 = 0.f, d1 = 0.f, d2 = 0.f;
        for (int j = lane; j < Hn; j += 32) {
            float kv = kp[j];
            float p  = kv * qrow[j];
            sk += kv; sk2 += kv * kv; d1 += p; d2 += p * p;
        }
        #pragma unroll
        for (int o = 16; o; o >>= 1) {
            sk  += __shfl_xor_sync(0xffffffffu, sk,  o);
            sk2 += __shfl_xor_sync(0xffffffffu, sk2, o);
            d1  += __shfl_xor_sync(0xffffffffu, d1,  o);
            d2  += __shfl_xor_sync(0xffffffffu, d2,  o);
        }
        if (lane == 0) { muS[kk] = sk + d1; rsS[kk] = sk2 + d2; }
    }
    __syncthreads();
    if (t < 128) {
        float mu = (sqv[0] + muS[t]) * (1.f / C3n);
        float e2 = (sqv[1] + rsS[t]) * (1.f / C3n);
        muS[t] = mu;
        rsS[t] = rsqrtf(e2 - mu * mu + EPSf);
    }

    float partial[8] = {0.f, 0.f, 0.f, 0.f, 0.f, 0.f, 0.f, 0.f};
    const float bo_v = bo[0];

    ull accu[8][4], accv[8][4];

    for (int ht = 0; ht < 4; ht++) {
        const int h0 = ht * 128;
        __syncthreads();  // previous epilogue reads done before overwriting h-arrays
        if (t < 128) {
            ruqS[t] = g_ruq[bq * Hn + h0 + t];
            rvqS[t] = g_rvq[bq * Hn + h0 + t];
            guS[t]  = g_gu[h0 + t];
            cuS[t]  = g_cu[h0 + t];
            gvS[t]  = g_gv[h0 + t];
            cvS[t]  = g_cv[h0 + t];
            woS[t]  = Wo[h0 + t];
        }
        #pragma unroll
        for (int i = 0; i < 8; i++)
            #pragma unroll
            for (int p = 0; p < 4; p++) { accu[i][p] = 0ull; accv[i][p] = 0ull; }

        for (int jc = 0; jc < 32; jc++) {
            const int j0 = jc * 16;
            // stage: KsT[j][k] = kproj[k][j0+j] * qrow[j0+j]; BuS/BvS = C^T tiles
            #pragma unroll
            for (int pp = 0; pp < 2; pp++) {
                int e  = t + pp * 256;
                int kk = e >> 2;
                int jq = e & 3;
                float4 kv = *(const float4*)(kpbase + kk * Hn + j0 + jq * 4);
                float4 qv = *(const float4*)&qrow[j0 + jq * 4];
                KsT[jq * 4 + 0][kk] = kv.x * qv.x;
                KsT[jq * 4 + 1][kk] = kv.y * qv.y;
                KsT[jq * 4 + 2][kk] = kv.z * qv.z;
                KsT[jq * 4 + 3][kk] = kv.w * qv.w;
                int j  = e >> 5;
                int hq = e & 31;
                *(float4*)&BuS[j][hq * 4] = *(const float4*)&g_CuT[(j0 + j) * Hn + h0 + hq * 4];
                *(float4*)&BvS[j][hq * 4] = *(const float4*)&g_CvT[(j0 + j) * Hn + h0 + hq * 4];
            }
            __syncthreads();
            #pragma unroll
            for (int jj = 0; jj < 16; jj++) {
                float4 a0 = *(const float4*)&KsT[jj][ty * 8];
                float4 a1 = *(const float4*)&KsT[jj][ty * 8 + 4];
                ulonglong2 u0 = *(const ulonglong2*)&BuS[jj][tx * 4];
                ulonglong2 u1 = *(const ulonglong2*)&BuS[jj][64 + tx * 4];
                ulonglong2 v0 = *(const ulonglong2*)&BvS[jj][tx * 4];
                ulonglong2 v1 = *(const ulonglong2*)&BvS[jj][64 + tx * 4];
                float av[8] = {a0.x, a0.y, a0.z, a0.w, a1.x, a1.y, a1.z, a1.w};
                #pragma unroll
                for (int i = 0; i < 8; i++) {
                    ull aa = pack2(av[i]);
                    accu[i][0] = fma2(aa, u0.x, accu[i][0]);
                    accu[i][1] = fma2(aa, u0.y, accu[i][1]);
                    accu[i][2] = fma2(aa, u1.x, accu[i][2]);
                    accu[i][3] = fma2(aa, u1.y, accu[i][3]);
                    accv[i][0] = fma2(aa, v0.x, accv[i][0]);
                    accv[i][1] = fma2(aa, v0.y, accv[i][1]);
                    accv[i][2] = fma2(aa, v1.x, accv[i][2]);
                    accv[i][3] = fma2(aa, v1.y, accv[i][3]);
                }
            }
            __syncthreads();
        }

        // epilogue: LN affine terms + gated gelu + Wo-weighted reduce over h
        #pragma unroll
        for (int i = 0; i < 8; i++) {
            const int kl  = ty * 8 + i;
            const float mu = muS[kl];
            const float rs = rsS[kl];
            const float mrs = mu * rs;
            const int kg = b * KLn + k0 + kl;
            const float4* ruk4 = (const float4*)(g_ruk + kg * Hn + h0);
            const float4* rvk4 = (const float4*)(g_rvk + kg * Hn + h0);
            float4 ruA = ruk4[tx], ruB = ruk4[16 + tx];
            float4 rvA = rvk4[tx], rvB = rvk4[16 + tx];
            float rukv[8] = {ruA.x, ruA.y, ruA.z, ruA.w, ruB.x, ruB.y, ruB.z, ruB.w};
            float rvkv[8] = {rvA.x, rvA.y, rvA.z, rvA.w, rvB.x, rvB.y, rvB.z, rvB.w};
            float tu[8], tv[8];
            float2 f;
            f = unpack2(accu[i][0]); tu[0] = f.x; tu[1] = f.y;
            f = unpack2(accu[i][1]); tu[2] = f.x; tu[3] = f.y;
            f = unpack2(accu[i][2]); tu[4] = f.x; tu[5] = f.y;
            f = unpack2(accu[i][3]); tu[6] = f.x; tu[7] = f.y;
            f = unpack2(accv[i][0]); tv[0] = f.x; tv[1] = f.y;
            f = unpack2(accv[i][1]); tv[2] = f.x; tv[3] = f.y;
            f = unpack2(accv[i][2]); tv[4] = f.x; tv[5] = f.y;
            f = unpack2(accv[i][3]); tv[6] = f.x; tv[7] = f.y;
            #pragma unroll
            for (int e = 0; e < 8; e++) {
                int h = (e < 4) ? (tx * 4 + e) : (64 + tx * 4 + (e - 4));
                float U = rs * (tu[e] + ruqS[h] + rukv[e]) - mrs * guS[h] + cuS[h];
                float V = rs * (tv[e] + rvqS[h] + rvkv[e]) - mrs * gvS[h] + cvS[h];
                float G = 0.5f * V * (1.0f + erff(V * 0.70710678118654752440f));
                partial[i] += woS[h] * (U * G);
            }
        }
    }

    // reduce partials across the 16 tx lanes (contiguous half-warp groups)
    #pragma unroll
    for (int i = 0; i < 8; i++) {
        float v = partial[i];
        #pragma unroll
        for (int o = 8; o; o >>= 1) v += __shfl_xor_sync(0xffffffffu, v, o);
        if (tx == 0) out[bq * KLn + k0 + ty * 8 + i] = v + bo_v;
    }
}

// ---------------- launch ----------------
extern "C" void kernel_launch(void* const* d_in, const int* in_sizes, int n_in,
                              void* d_out, int out_size) {
    const float* Q   = (const float*)d_in[0];
    const float* K   = (const float*)d_in[1];
    const float* Wq  = (const float*)d_in[2];
    const float* Wk  = (const float*)d_in[3];
    const float* lnw = (const float*)d_in[4];
    const float* lnb = (const float*)d_in[5];
    const float* Wu  = (const float*)d_in[6];
    const float* bu  = (const float*)d_in[7];
    const float* Wv  = (const float*)d_in[8];
    const float* bv  = (const float*)d_in[9];
    const float* Wo  = (const float*)d_in[10];
    const float* bo  = (const float*)d_in[11];
    float* out = (float*)d_out;

    void *p_wqt, *p_wkt, *p_aut, *p_avt, *p_but, *p_bvt;
    void *p_qp, *p_kp, *p_ruq, *p_rvq, *p_ruk, *p_rvk;
    cudaGetSymbolAddress(&p_wqt, g_WqT);
    cudaGetSymbolAddress(&p_wkt, g_WkT);
    cudaGetSymbolAddress(&p_aut, g_AuT);
    cudaGetSymbolAddress(&p_avt, g_AvT);
    cudaGetSymbolAddress(&p_but, g_BuT);
    cudaGetSymbolAddress(&p_bvt, g_BvT);
    cudaGetSymbolAddress(&p_qp,  g_qproj);
    cudaGetSymbolAddress(&p_kp,  g_kproj);
    cudaGetSymbolAddress(&p_ruq, g_ruq);
    cudaGetSymbolAddress(&p_rvq, g_rvq);
    cudaGetSymbolAddress(&p_ruk, g_ruk);
    cudaGetSymbolAddress(&p_rvk, g_rvk);

    prep_transpose<<<512, 256>>>(Wq, Wk);
    prep_split<<<512, 256>>>(Wu, Wv, lnw);
    prep_vec<<<64, 256>>>(Wu, bu, Wv, bv, lnw, lnb);

    dim3 g88(8, 8);
    gemm_rm<<<g88, 256>>>(Q, (const float*)p_wqt, (float*)p_qp, Bb * QLn, Hn, QDn);
    gemm_rm<<<g88, 256>>>(K, (const float*)p_wkt, (float*)p_kp, Bb * KLn, Hn, QDn);
    gemm_rm<<<g88, 256>>>((const float*)p_qp, (const float*)p_aut, (float*)p_ruq, Bb * QLn, Hn, Hn);
    gemm_rm<<<g88, 256>>>((const float*)p_qp, (const float*)p_avt, (float*)p_rvq, Bb * QLn, Hn, Hn);
    gemm_rm<<<g88, 256>>>((const float*)p_kp, (const float*)p_but, (float*)p_ruk, Bb * KLn, Hn, Hn);
    gemm_rm<<<g88, 256>>>((const float*)p_kp, (const float*)p_bvt, (float*)p_rvk, Bb * KLn, Hn, Hn);

    gated_main<<<dim3(2, 512), 256>>>(Wo, bo, out);
}

// round 4
// speedup vs baseline: 2.7099x; 2.7099x over previous
#include <cuda_runtime.h>
#include <cstdint>

#define Bb   2
#define QLn  256
#define KLn  256
#define QDn  1024
#define Hn   512
#define C3n  1536
#define EPSf 1e-5f

typedef unsigned long long ull;
typedef unsigned int u32;

// ---------------- device scratch (static, no allocation) ----------------
__device__ __align__(16) float g_WqT[QDn*Hn];
__device__ __align__(16) float g_WkT[QDn*Hn];
__device__ __align__(16) float g_AuT[Hn*Hn];     // [j][h] = Wu[h, j]    * lnw[j]
__device__ __align__(16) float g_BuT[Hn*Hn];     // [j][h] = Wu[h, H+j]  * lnw[H+j]
__device__ __align__(16) float g_AvT[Hn*Hn];
__device__ __align__(16) float g_BvT[Hn*Hn];
__device__ __align__(16) u32   g_CuF[262144];    // tf32 A-fragment pack of Cu'
__device__ __align__(16) u32   g_CvF[262144];
__device__ __align__(16) u32   g_KsF[67108864];  // tf32 B-fragment pack of q(x)k, per (bq, k-half)
__device__ __align__(16) float g_gu[Hn], g_cu[Hn], g_gv[Hn], g_cv[Hn];
__device__ __align__(16) float g_qproj[Bb*QLn*Hn];
__device__ __align__(16) float g_kproj[Bb*KLn*Hn];
__device__ __align__(16) float g_ruq[Bb*QLn*Hn];
__device__ __align__(16) float g_rvq[Bb*QLn*Hn];
__device__ __align__(16) float g_ruk[Bb*KLn*Hn];
__device__ __align__(16) float g_rvk[Bb*KLn*Hn];
__device__ __align__(16) float g_mu[Bb*QLn*KLn];
__device__ __align__(16) float g_rs[Bb*QLn*KLn];

// ---------------- asm helpers ----------------
__device__ __forceinline__ u32 tf32r(float f) {
    u32 u; asm("cvt.rna.tf32.f32 %0, %1;" : "=r"(u) : "f"(f)); return u;
}
__device__ __forceinline__ u32 smem_u32(const void* p) {
    u32 a;
    asm("{ .reg .u64 t; cvta.to.shared.u64 t, %1; cvt.u32.u64 %0, t; }" : "=r"(a) : "l"(p));
    return a;
}
__device__ __forceinline__ void cpasync16(u32 s, const void* g) {
    asm volatile("cp.async.cg.shared.global [%0], [%1], 16;" :: "r"(s), "l"(g));
}
__device__ __forceinline__ void cp_commit() { asm volatile("cp.async.commit_group;" ::: "memory"); }
__device__ __forceinline__ void cp_wait1()  { asm volatile("cp.async.wait_group 1;" ::: "memory"); }
__device__ __forceinline__ void cp_wait0()  { asm volatile("cp.async.wait_group 0;" ::: "memory"); }
__device__ __forceinline__ void lds128(u32 a, u32* r) {
    asm volatile("ld.shared.v4.b32 {%0,%1,%2,%3}, [%4];"
                 : "=r"(r[0]), "=r"(r[1]), "=r"(r[2]), "=r"(r[3]) : "r"(a));
}
__device__ __forceinline__ void lds64(u32 a, u32* r) {
    asm volatile("ld.shared.v2.b32 {%0,%1}, [%2];" : "=r"(r[0]), "=r"(r[1]) : "r"(a));
}
// D[m=16 h][n=8 k] += A[16x8 tf32] * B[8x8 tf32]
__device__ __forceinline__ void mma8(float* d, const u32* a, const u32* b) {
    asm volatile(
        "mma.sync.aligned.m16n8k8.row.col.f32.tf32.tf32.f32 "
        "{%0,%1,%2,%3}, {%4,%5,%6,%7}, {%8,%9}, {%0,%1,%2,%3};"
        : "+f"(d[0]), "+f"(d[1]), "+f"(d[2]), "+f"(d[3])
        : "r"(a[0]), "r"(a[1]), "r"(a[2]), "r"(a[3]), "r"(b[0]), "r"(b[1]));
}

// ---------------- prep kernels ----------------
__global__ void prep_transpose(const float* __restrict__ Wq, const float* __restrict__ Wk) {
    int stride = gridDim.x * blockDim.x;
    for (int i = blockIdx.x * blockDim.x + threadIdx.x; i < QDn * Hn; i += stride) {
        int d = i / Hn, h = i - d * Hn;
        g_WqT[i] = Wq[h * QDn + d];
        g_WkT[i] = Wk[h * QDn + d];
    }
}

__global__ void prep_split(const float* __restrict__ Wu, const float* __restrict__ Wv,
                           const float* __restrict__ lnw) {
    int stride = gridDim.x * blockDim.x;
    for (int i = blockIdx.x * blockDim.x + threadIdx.x; i < Hn * Hn; i += stride) {
        int j = i / Hn, h = i - j * Hn;
        float w0 = lnw[j], w1 = lnw[Hn + j];
        g_AuT[i] = Wu[h * C3n + j] * w0;       g_AvT[i] = Wv[h * C3n + j] * w0;
        g_BuT[i] = Wu[h * C3n + Hn + j] * w1;  g_BvT[i] = Wv[h * C3n + Hn + j] * w1;
    }
}

// A-fragment pack: w = ((((ht*16+jc)*8+mtl)*4+kt)*32+lane)*4 + r
// value = tf32( Wu[h][2H+j] * lnw[2H+j] ), h = ht*128+mtl*16+(lane>>2)+8*(r&1),
//                                          j = jc*32+kt*8+(lane&3)+4*(r>>1)
__global__ void prep_pack(const float* __restrict__ Wu, const float* __restrict__ Wv,
                          const float* __restrict__ lnw) {
    int stride = gridDim.x * blockDim.x;
    for (int w = blockIdx.x * blockDim.x + threadIdx.x; w < 262144; w += stride) {
        int r = w & 3, lane = (w >> 2) & 31, kt = (w >> 7) & 3, mtl = (w >> 9) & 7;
        int jc = (w >> 12) & 15, ht = w >> 16;
        int h = ht * 128 + mtl * 16 + (lane >> 2) + 8 * (r & 1);
        int j = jc * 32 + kt * 8 + (lane & 3) + 4 * (r >> 1);
        float wl = lnw[2 * Hn + j];
        g_CuF[w] = tf32r(Wu[h * C3n + 2 * Hn + j] * wl);
        g_CvF[w] = tf32r(Wv[h * C3n + 2 * Hn + j] * wl);
    }
}

__global__ void prep_vec(const float* __restrict__ Wu, const float* __restrict__ bu,
                         const float* __restrict__ Wv, const float* __restrict__ bv,
                         const float* __restrict__ lnw, const float* __restrict__ lnb) {
    int w = (blockIdx.x * blockDim.x + threadIdx.x) >> 5;
    int lane = threadIdx.x & 31;
    if (w >= Hn) return;
    float gu = 0.f, cu = 0.f, gv = 0.f, cv = 0.f;
    for (int c = lane; c < C3n; c += 32) {
        float wl = lnw[c], bl = lnb[c];
        float a = Wu[w * C3n + c], d = Wv[w * C3n + c];
        gu += a * wl; cu += a * bl; gv += d * wl; cv += d * bl;
    }
    #pragma unroll
    for (int o = 16; o; o >>= 1) {
        gu += __shfl_xor_sync(0xffffffffu, gu, o);
        cu += __shfl_xor_sync(0xffffffffu, cu, o);
        gv += __shfl_xor_sync(0xffffffffu, gv, o);
        cv += __shfl_xor_sync(0xffffffffu, cv, o);
    }
    if (lane == 0) {
        g_gu[w] = gu; g_cu[w] = cu + bu[w];
        g_gv[w] = gv; g_cv[w] = cv + bv[w];
    }
}

// ---------------- fp32 GEMM (prep projections) ----------------
__device__ __forceinline__ void gemm_body(const float* __restrict__ A,
                                          const float* __restrict__ Bm,
                                          float* __restrict__ C, int N, int Kd) {
    __shared__ __align__(16) float As[16][68];
    __shared__ __align__(16) float Bs[16][68];
    const int t  = threadIdx.x;
    const int tx = t & 15, ty = t >> 4;
    const int bm = blockIdx.y * 64, bn = blockIdx.x * 64;
    float acc[4][4] = {};
    for (int kb = 0; kb < Kd; kb += 16) {
        #pragma unroll
        for (int l = 0; l < 4; l++) {
            int e = t + l * 256;
            int m = e >> 4, kk = e & 15;
            As[kk][m] = A[(bm + m) * Kd + kb + kk];
            int n = e & 63, k2 = e >> 6;
            Bs[k2][n] = Bm[(kb + k2) * N + bn + n];
        }
        __syncthreads();
        #pragma unroll
        for (int kk = 0; kk < 16; kk++) {
            float4 a = *(const float4*)&As[kk][ty * 4];
            float4 b = *(const float4*)&Bs[kk][tx * 4];
            float aw[4] = {a.x, a.y, a.z, a.w};
            float bw[4] = {b.x, b.y, b.z, b.w};
            #pragma unroll
            for (int i = 0; i < 4; i++)
                #pragma unroll
                for (int j = 0; j < 4; j++)
                    acc[i][j] += aw[i] * bw[j];
        }
        __syncthreads();
    }
    #pragma unroll
    for (int i = 0; i < 4; i++) {
        float4 o = make_float4(acc[i][0], acc[i][1], acc[i][2], acc[i][3]);
        *(float4*)&C[(bm + ty * 4 + i) * N + bn + tx * 4] = o;
    }
}

__global__ __launch_bounds__(256) void gemm_proj(const float* __restrict__ Q,
                                                 const float* __restrict__ K) {
    if (blockIdx.z == 0) gemm_body(Q, g_WqT, g_qproj, Hn, QDn);
    else                 gemm_body(K, g_WkT, g_kproj, Hn, QDn);
}

__global__ __launch_bounds__(256) void gemm_hid() {
    switch (blockIdx.z) {
        case 0:  gemm_body(g_qproj, g_AuT, g_ruq, Hn, Hn); break;
        case 1:  gemm_body(g_qproj, g_AvT, g_rvq, Hn, Hn); break;
        case 2:  gemm_body(g_kproj, g_BuT, g_ruk, Hn, Hn); break;
        default: gemm_body(g_kproj, g_BvT, g_rvk, Hn, Hn); break;
    }
}

// ---------------- per-pair LN stats ----------------
__global__ __launch_bounds__(256) void stats_kernel() {
    __shared__ __align__(16) float qrow[Hn];
    __shared__ float s1s[128], s2s[128], sqv[2];
    const int t = threadIdx.x, warp = t >> 5, lane = t & 31;
    const int bq = blockIdx.y, b = bq >> 8;
    const int k0 = blockIdx.x * 128;
    const float* qp = g_qproj + bq * Hn;
    qrow[t] = qp[t]; qrow[t + 256] = qp[t + 256];
    __syncthreads();
    if (warp == 0) {
        float s1 = 0.f, s2 = 0.f;
        #pragma unroll
        for (int j = lane; j < Hn; j += 32) { float v = qrow[j]; s1 += v; s2 += v * v; }
        #pragma unroll
        for (int o = 16; o; o >>= 1) {
            s1 += __shfl_xor_sync(0xffffffffu, s1, o);
            s2 += __shfl_xor_sync(0xffffffffu, s2, o);
        }
        if (lane == 0) { sqv[0] = s1; sqv[1] = s2; }
    }
    const float* kpbase = g_kproj + (b * KLn + k0) * Hn;
    for (int r = 0; r < 16; r++) {
        int kk = warp * 16 + r;
        const float* kp = kpbase + kk * Hn;
        float sk = 0.f, sk2 = 0.f, d1 = 0.f, d2 = 0.f;
        for (int j = lane; j < Hn; j += 32) {
            float kv = kp[j];
            float p  = kv * qrow[j];
            sk += kv; sk2 += kv * kv; d1 += p; d2 += p * p;
        }
        #pragma unroll
        for (int o = 16; o; o >>= 1) {
            sk  += __shfl_xor_sync(0xffffffffu, sk,  o);
            sk2 += __shfl_xor_sync(0xffffffffu, sk2, o);
            d1  += __shfl_xor_sync(0xffffffffu, d1,  o);
            d2  += __shfl_xor_sync(0xffffffffu, d2,  o);
        }
        if (lane == 0) { s1s[kk] = sk + d1; s2s[kk] = sk2 + d2; }
    }
    __syncthreads();
    if (t < 128) {
        float mu = (sqv[0] + s1s[t]) * (1.f / C3n);
        float e2 = (sqv[1] + s2s[t]) * (1.f / C3n);
        g_mu[bq * KLn + k0 + t] = mu;
        g_rs[bq * KLn + k0 + t] = rsqrtf(e2 - mu * mu + EPSf);
    }
}

// ---------------- Ks fragment pack ----------------
// per (bq, kh): [jc 16][ntc 16][kt 4][lane 32][r 2]; value = tf32(kproj[k][j]*q[j])
// k = kh*128 + ntc*8 + (lane>>2), j = jc*32 + kt*8 + (lane&3) + 4r
__global__ __launch_bounds__(256) void ks_pack() {
    __shared__ __align__(16) float qrow[Hn];
    const int t = threadIdx.x;
    const int key = blockIdx.x;
    const int bq = key >> 1, kh = key & 1, b = bq >> 8;
    const float* qp = g_qproj + bq * Hn;
    qrow[t] = qp[t]; qrow[t + 256] = qp[t + 256];
    __syncthreads();
    u32* dst = g_KsF + (size_t)key * 65536;
    const float* kp = g_kproj + (size_t)(b * KLn + kh * 128) * Hn;
    for (int jc = 0; jc < 16; jc++) {
        #pragma unroll
        for (int i = 0; i < 8; i++) {
            int pidx = t + i * 256;          // pair index 0..2047
            int lane = pidx & 31;
            int kt   = (pidx >> 5) & 3;
            int ntc  = pidx >> 7;
            int k  = ntc * 8 + (lane >> 2);
            int j0 = jc * 32 + kt * 8 + (lane & 3);
            float kv0 = kp[k * Hn + j0];
            float kv1 = kp[k * Hn + j0 + 4];
            dst[jc * 4096 + pidx * 2]     = tf32r(kv0 * qrow[j0]);
            dst[jc * 4096 + pidx * 2 + 1] = tf32r(kv1 * qrow[j0 + 4]);
        }
    }
}

// ---------------- main mma.sync kernel ----------------
// grid (2, 512) = (k-half, bq). 256 threads = 8 warps: hg=warp&3 (32h), kg=warp>>2 (64k).
// ht loop: 4 chunks of 128 h. D[m=h][n=k] += C'[h,j] * Ks[j,k].
#define OFF_BUF 0
#define BUF_SZ  49152
#define OFF_HV  98304
#define OFF_MU  101888
#define OFF_RS  102400
#define OFF_SP  102912
#define SM_SZ   104960

__global__ __launch_bounds__(256, 1) void gated_mma(const float* __restrict__ Wo,
                                                    const float* __restrict__ bo,
                                                    float* __restrict__ out) {
    extern __shared__ __align__(16) char sm[];
    const u32 sb = smem_u32(sm);
    const int t = threadIdx.x, lane = t & 31, warp = t >> 5;
    const int hg = warp & 3, kg = warp >> 2;
    const int q = lane >> 2, tid = lane & 3;
    const int kh = blockIdx.x, bq = blockIdx.y, b = bq >> 8;

    float* muS = (float*)(sm + OFF_MU);
    float* rsS = (float*)(sm + OFF_RS);
    if (t < 128) {
        muS[t] = g_mu[bq * KLn + kh * 128 + t];
        rsS[t] = g_rs[bq * KLn + kh * 128 + t];
    }

    float accU[2][8][4] = {}, accV[2][8][4] = {};
    float part[8][2] = {};

    const u32* srcB0 = g_KsF + (size_t)(bq * 2 + kh) * 65536;

    auto stage = [&](int it) {
        int ht = it >> 4, jc = it & 15;
        u32 dst = sb + OFF_BUF + (u32)(it & 1) * BUF_SZ;
        const char* su = (const char*)(g_CuF + (ht * 16 + jc) * 4096);
        const char* sv = (const char*)(g_CvF + (ht * 16 + jc) * 4096);
        const char* sk = (const char*)(srcB0 + jc * 4096);
        #pragma unroll
        for (int i = 0; i < 4; i++) {
            int u = t + i * 256;
            cpasync16(dst + u * 16,         su + u * 16);
            cpasync16(dst + 16384 + u * 16, sv + u * 16);
            cpasync16(dst + 32768 + u * 16, sk + u * 16);
        }
        cp_commit();
    };

    stage(0);
    for (int it = 0; it < 64; it++) {
        if (it < 63) { stage(it + 1); cp_wait1(); }
        else         { cp_wait0(); }
        __syncthreads();

        const u32 bufb = sb + OFF_BUF + (u32)(it & 1) * BUF_SZ;
        const u32 aU = bufb, aV = bufb + 16384, bB = bufb + 32768;

        #pragma unroll
        for (int kt = 0; kt < 4; kt++) {
            u32 au0[4], au1[4], av0[4], av1[4];
            lds128(aU + (u32)(((hg * 2 + 0) * 4 + kt) * 32 + lane) * 16, au0);
            lds128(aU + (u32)(((hg * 2 + 1) * 4 + kt) * 32 + lane) * 16, au1);
            lds128(aV + (u32)(((hg * 2 + 0) * 4 + kt) * 32 + lane) * 16, av0);
            lds128(aV + (u32)(((hg * 2 + 1) * 4 + kt) * 32 + lane) * 16, av1);
            #pragma unroll
            for (int nt = 0; nt < 8; nt++) {
                u32 bf[2];
                lds64(bB + (u32)((((kg * 8 + nt) * 4 + kt) * 32) + lane) * 8, bf);
                mma8(accU[0][nt], au0, bf);
                mma8(accU[1][nt], au1, bf);
                mma8(accV[0][nt], av0, bf);
                mma8(accV[1][nt], av1, bf);
            }
        }

        if ((it & 15) == 15) {
            const int ht = it >> 4;
            __syncthreads();
            float* hv = (float*)(sm + OFF_HV);
            if (t < 128) {
                hv[t]       = g_ruq[bq * Hn + ht * 128 + t];
                hv[128 + t] = g_rvq[bq * Hn + ht * 128 + t];
                hv[256 + t] = g_gu[ht * 128 + t];
                hv[384 + t] = g_cu[ht * 128 + t];
                hv[512 + t] = g_gv[ht * 128 + t];
                hv[640 + t] = g_cv[ht * 128 + t];
                hv[768 + t] = Wo[ht * 128 + t];
            }
            __syncthreads();
            const float* rubase = g_ruk + (b * KLn + kh * 128) * Hn + ht * 128;
            const float* rvbase = g_rvk + (b * KLn + kh * 128) * Hn + ht * 128;
            #pragma unroll
            for (int mt = 0; mt < 2; mt++) {
                #pragma unroll
                for (int rr = 0; rr < 2; rr++) {
                    const int hl = (hg * 2 + mt) * 16 + q + rr * 8;
                    const float ruq = hv[hl],       rvq = hv[128 + hl];
                    const float gu  = hv[256 + hl], cu  = hv[384 + hl];
                    const float gv  = hv[512 + hl], cv  = hv[640 + hl];
                    const float wo  = hv[768 + hl];
                    #pragma unroll
                    for (int nt = 0; nt < 8; nt++) {
                        #pragma unroll
                        for (int e = 0; e < 2; e++) {
                            const int kc = kg * 64 + nt * 8 + tid * 2 + e;
                            const float mu = muS[kc], rs = rsS[kc];
                            const float du = accU[mt][nt][rr * 2 + e];
                            const float dv = accV[mt][nt][rr * 2 + e];
                            const float ruk = rubase[kc * Hn + hl];
                            const float rvk = rvbase[kc * Hn + hl];
                            float U = rs * (du + ruq + ruk) - mu * rs * gu + cu;
                            float V = rs * (dv + rvq + rvk) - mu * rs * gv + cv;
                            float G = 0.5f * V * (1.0f + erff(V * 0.70710678118654752440f));
                            part[nt][e] += wo * (U * G);
                            accU[mt][nt][rr * 2 + e] = 0.f;
                            accV[mt][nt][rr * 2 + e] = 0.f;
                        }
                    }
                }
            }
        }
        __syncthreads();
    }

    // reduce across q-lanes (same tid), then across hg warps via smem
    #pragma unroll
    for (int nt = 0; nt < 8; nt++)
        #pragma unroll
        for (int e = 0; e < 2; e++) {
            float v = part[nt][e];
            v += __shfl_xor_sync(0xffffffffu, v, 4);
            v += __shfl_xor_sync(0xffffffffu, v, 8);
            v += __shfl_xor_sync(0xffffffffu, v, 16);
            part[nt][e] = v;
        }
    float* sp = (float*)(sm + OFF_SP);
    if (q == 0) {
        #pragma unroll
        for (int nt = 0; nt < 8; nt++)
            #pragma unroll
            for (int e = 0; e < 2; e++)
                sp[hg * 128 + kg * 64 + nt * 8 + tid * 2 + e] = part[nt][e];
    }
    __syncthreads();
    if (t < 128) {
        float r = sp[t] + sp[128 + t] + sp[256 + t] + sp[384 + t] + bo[0];
        out[bq * KLn + kh * 128 + t] = r;
    }
}

// ---------------- launch ----------------
extern "C" void kernel_launch(void* const* d_in, const int* in_sizes, int n_in,
                              void* d_out, int out_size) {
    const float* Q   = (const float*)d_in[0];
    const float* K   = (const float*)d_in[1];
    const float* Wq  = (const float*)d_in[2];
    const float* Wk  = (const float*)d_in[3];
    const float* lnw = (const float*)d_in[4];
    const float* lnb = (const float*)d_in[5];
    const float* Wu  = (const float*)d_in[6];
    const float* bu  = (const float*)d_in[7];
    const float* Wv  = (const float*)d_in[8];
    const float* bv  = (const float*)d_in[9];
    const float* Wo  = (const float*)d_in[10];
    const float* bo  = (const float*)d_in[11];
    float* out = (float*)d_out;

    static int smem_set = 0;
    if (!smem_set) {
        cudaFuncSetAttribute(gated_mma, cudaFuncAttributeMaxDynamicSharedMemorySize, SM_SZ);
        smem_set = 1;
    }

    prep_transpose<<<512, 256>>>(Wq, Wk);
    prep_split<<<512, 256>>>(Wu, Wv, lnw);
    prep_pack<<<256, 256>>>(Wu, Wv, lnw);
    prep_vec<<<64, 256>>>(Wu, bu, Wv, bv, lnw, lnb);

    gemm_proj<<<dim3(8, 8, 2), 256>>>(Q, K);
    gemm_hid<<<dim3(8, 8, 4), 256>>>();
    stats_kernel<<<dim3(2, 512), 256>>>();
    ks_pack<<<1024, 256>>>();

    gated_mma<<<dim3(2, 512), 256, SM_SZ>>>(Wo, bo, out);
}

// round 5
// speedup vs baseline: 2.7294x; 1.0072x over previous
#include <cuda_runtime.h>
#include <cstdint>

#define Bb   2
#define QLn  256
#define KLn  256
#define QDn  1024
#define Hn   512
#define C3n  1536
#define EPSf 1e-5f

typedef unsigned long long ull;
typedef unsigned int u32;

// ---------------- device scratch (static, no allocation) ----------------
__device__ __align__(16) float g_WqT[QDn*Hn];
__device__ __align__(16) float g_WkT[QDn*Hn];
__device__ __align__(16) float g_AuT[Hn*Hn];     // [j][h] = Wu[h, j]   * lnw[j]
__device__ __align__(16) float g_AvT[Hn*Hn];
__device__ __align__(16) float g_Bu[Hn*Hn];      // [h][j] = Wu[h, H+j] * lnw[H+j]
__device__ __align__(16) float g_Bv[Hn*Hn];
__device__ __align__(16) u32   g_CuF[262144];    // tf32 A-fragment pack of Cu'
__device__ __align__(16) u32   g_CvF[262144];
__device__ __align__(16) float g_gu[Hn], g_cu[Hn], g_gv[Hn], g_cv[Hn];
__device__ __align__(16) float g_qproj[Bb*QLn*Hn];
__device__ __align__(16) float g_kproj[Bb*KLn*Hn];
__device__ __align__(16) float g_ruq[Bb*QLn*Hn];
__device__ __align__(16) float g_rvq[Bb*QLn*Hn];
__device__ __align__(16) float g_rukT[Bb*Hn*KLn];   // [b][h][k]
__device__ __align__(16) float g_rvkT[Bb*Hn*KLn];
__device__ __align__(16) float g_mu[Bb*QLn*KLn];
__device__ __align__(16) float g_rs[Bb*QLn*KLn];

// ---------------- asm helpers ----------------
__device__ __forceinline__ u32 tf32r(float f) {
    u32 u; asm("cvt.rna.tf32.f32 %0, %1;" : "=r"(u) : "f"(f)); return u;
}
__device__ __forceinline__ u32 smem_u32(const void* p) {
    u32 a;
    asm("{ .reg .u64 t; cvta.to.shared.u64 t, %1; cvt.u32.u64 %0, t; }" : "=r"(a) : "l"(p));
    return a;
}
__device__ __forceinline__ void cpasync16(u32 s, const void* g) {
    asm volatile("cp.async.cg.shared.global [%0], [%1], 16;" :: "r"(s), "l"(g));
}
__device__ __forceinline__ void cp_commit() { asm volatile("cp.async.commit_group;" ::: "memory"); }
__device__ __forceinline__ void cp_wait1()  { asm volatile("cp.async.wait_group 1;" ::: "memory"); }
__device__ __forceinline__ void cp_wait0()  { asm volatile("cp.async.wait_group 0;" ::: "memory"); }
__device__ __forceinline__ void lds128(u32 a, u32* r) {
    asm volatile("ld.shared.v4.b32 {%0,%1,%2,%3}, [%4];"
                 : "=r"(r[0]), "=r"(r[1]), "=r"(r[2]), "=r"(r[3]) : "r"(a));
}
__device__ __forceinline__ void lds64(u32 a, u32* r) {
    asm volatile("ld.shared.v2.b32 {%0,%1}, [%2];" : "=r"(r[0]), "=r"(r[1]) : "r"(a));
}
// D[m=16 h][n=8 k] += A[16x8 tf32] * B[8x8 tf32]
__device__ __forceinline__ void mma8(float* d, const u32* a, const u32* b) {
    asm volatile(
        "mma.sync.aligned.m16n8k8.row.col.f32.tf32.tf32.f32 "
        "{%0,%1,%2,%3}, {%4,%5,%6,%7}, {%8,%9}, {%0,%1,%2,%3};"
        : "+f"(d[0]), "+f"(d[1]), "+f"(d[2]), "+f"(d[3])
        : "r"(a[0]), "r"(a[1]), "r"(a[2]), "r"(a[3]), "r"(b[0]), "r"(b[1]));
}

// ---------------- merged prep kernel (z: 0 WqT, 1 WkT, 2 split, 3 pack, 4 vec) ----
__global__ __launch_bounds__(256) void prep_w(const float* __restrict__ Wq,
                                              const float* __restrict__ Wk,
                                              const float* __restrict__ Wu,
                                              const float* __restrict__ Wv,
                                              const float* __restrict__ lnw,
                                              const float* __restrict__ lnb,
                                              const float* __restrict__ bu,
                                              const float* __restrict__ bv) {
    __shared__ float T[32][33];
    const int t = threadIdx.x, z = blockIdx.z;
    if (z < 2) {
        const float* W = (z == 0) ? Wq : Wk;
        float* WT = (z == 0) ? g_WqT : g_WkT;
        const int x = t & 31, y8 = t >> 5;
        const int th = (blockIdx.x & 15) * 32;   // h tile
        const int td = (blockIdx.x >> 4) * 32;   // d tile
        #pragma unroll
        for (int r = 0; r < 4; r++) {
            int y = y8 + r * 8;
            T[y][x] = W[(size_t)(th + y) * QDn + td + x];
        }
        __syncthreads();
        #pragma unroll
        for (int r = 0; r < 4; r++) {
            int y = y8 + r * 8;
            WT[(size_t)(td + y) * Hn + th + x] = T[x][y];
        }
    } else if (z == 2) {
        for (int i = blockIdx.x * 256 + t; i < Hn * Hn; i += 512 * 256) {
            int h = i & (Hn - 1), j = i >> 9;
            float w0 = lnw[j];
            g_AuT[i] = Wu[(size_t)h * C3n + j] * w0;
            g_AvT[i] = Wv[(size_t)h * C3n + j] * w0;
        }
        for (int i = blockIdx.x * 256 + t; i < Hn * Hn; i += 512 * 256) {
            int j = i & (Hn - 1), h = i >> 9;
            float w1 = lnw[Hn + j];
            g_Bu[i] = Wu[(size_t)h * C3n + Hn + j] * w1;
            g_Bv[i] = Wv[(size_t)h * C3n + Hn + j] * w1;
        }
    } else if (z == 3) {
        // A-fragment pack: h = ht*128+mtl*16+(lane>>2)+8*(r&1), j = jc*32+kt*8+(lane&3)+4*(r>>1)
        for (int w = blockIdx.x * 256 + t; w < 262144; w += 512 * 256) {
            int r = w & 3, lane = (w >> 2) & 31, kt = (w >> 7) & 3, mtl = (w >> 9) & 7;
            int jc = (w >> 12) & 15, ht = w >> 16;
            int h = ht * 128 + mtl * 16 + (lane >> 2) + 8 * (r & 1);
            int j = jc * 32 + kt * 8 + (lane & 3) + 4 * (r >> 1);
            float wl = lnw[2 * Hn + j];
            g_CuF[w] = tf32r(Wu[(size_t)h * C3n + 2 * Hn + j] * wl);
            g_CvF[w] = tf32r(Wv[(size_t)h * C3n + 2 * Hn + j] * wl);
        }
    } else {
        int gw = blockIdx.x * 8 + (t >> 5);
        int lane = t & 31;
        if (gw >= Hn) return;
        float gu = 0.f, cu = 0.f, gv = 0.f, cv = 0.f;
        for (int c = lane; c < C3n; c += 32) {
            float wl = lnw[c], bl = lnb[c];
            float a = Wu[(size_t)gw * C3n + c], d = Wv[(size_t)gw * C3n + c];
            gu += a * wl; cu += a * bl; gv += d * wl; cv += d * bl;
        }
        #pragma unroll
        for (int o = 16; o; o >>= 1) {
            gu += __shfl_xor_sync(0xffffffffu, gu, o);
            cu += __shfl_xor_sync(0xffffffffu, cu, o);
            gv += __shfl_xor_sync(0xffffffffu, gv, o);
            cv += __shfl_xor_sync(0xffffffffu, cv, o);
        }
        if (lane == 0) {
            g_gu[gw] = gu; g_cu[gw] = cu + bu[gw];
            g_gv[gw] = gv; g_cv[gw] = cv + bv[gw];
        }
    }
}

// ---------------- fp32 GEMM body; NT: C[m][n] = sum_k A[m][k]*B[n][k] ----------------
template<bool NT>
__device__ __forceinline__ void gemm_body(const float* __restrict__ A,
                                          const float* __restrict__ Bm,
                                          float* __restrict__ C,
                                          int N, int Kd, int ldc) {
    __shared__ __align__(16) float As[16][68];
    __shared__ __align__(16) float Bs[16][68];
    const int t  = threadIdx.x;
    const int tx = t & 15, ty = t >> 4;
    const int bm = blockIdx.y * 64, bn = blockIdx.x * 64;
    float acc[4][4] = {};
    for (int kb = 0; kb < Kd; kb += 16) {
        #pragma unroll
        for (int l = 0; l < 4; l++) {
            int e = t + l * 256;
            int m = e >> 4, kk = e & 15;
            As[kk][m] = A[(size_t)(bm + m) * Kd + kb + kk];
            if (NT) {
                Bs[kk][m] = Bm[(size_t)(bn + m) * Kd + kb + kk];
            } else {
                int n = e & 63, k2 = e >> 6;
                Bs[k2][n] = Bm[(size_t)(kb + k2) * N + bn + n];
            }
        }
        __syncthreads();
        #pragma unroll
        for (int kk = 0; kk < 16; kk++) {
            float4 a = *(const float4*)&As[kk][ty * 4];
            float4 b = *(const float4*)&Bs[kk][tx * 4];
            float aw[4] = {a.x, a.y, a.z, a.w};
            float bw[4] = {b.x, b.y, b.z, b.w};
            #pragma unroll
            for (int i = 0; i < 4; i++)
                #pragma unroll
                for (int j = 0; j < 4; j++)
                    acc[i][j] += aw[i] * bw[j];
        }
        __syncthreads();
    }
    #pragma unroll
    for (int i = 0; i < 4; i++) {
        float4 o = make_float4(acc[i][0], acc[i][1], acc[i][2], acc[i][3]);
        *(float4*)&C[(size_t)(bm + ty * 4 + i) * ldc + bn + tx * 4] = o;
    }
}

__global__ __launch_bounds__(256) void gemm_proj(const float* __restrict__ Q,
                                                 const float* __restrict__ K) {
    if (blockIdx.z == 0) gemm_body<false>(Q, g_WqT, g_qproj, Hn, QDn, Hn);
    else                 gemm_body<false>(K, g_WkT, g_kproj, Hn, QDn, Hn);
}

// hidden-term GEMMs + LN stats in one launch. grid (8, 64, 7).
__global__ __launch_bounds__(256) void gemm_hs() {
    const int z = blockIdx.z;
    if (z < 6) {
        if (blockIdx.y >= 8) return;
        switch (z) {
            case 0: gemm_body<false>(g_qproj, g_AuT, g_ruq, Hn, Hn, Hn); return;
            case 1: gemm_body<false>(g_qproj, g_AvT, g_rvq, Hn, Hn, Hn); return;
            default: break;
        }
        if (blockIdx.x >= 4) return;
        const int b = (z - 2) >> 1;
        const float* kp = g_kproj + (size_t)b * KLn * Hn;
        if ((z & 1) == 0) gemm_body<true>(g_Bu, kp, g_rukT + (size_t)b * Hn * KLn, KLn, Hn, KLn);
        else              gemm_body<true>(g_Bv, kp, g_rvkT + (size_t)b * Hn * KLn, KLn, Hn, KLn);
        return;
    }
    // z == 6: LN stats; block handles one bq, all 256 k
    __shared__ __align__(16) float qrow[Hn];
    __shared__ float s1s[KLn], s2s[KLn], sqv[2];
    const int t = threadIdx.x, warp = t >> 5, lane = t & 31;
    const int bq = blockIdx.y * 8 + blockIdx.x;
    const int b = bq >> 8;
    const float* qp = g_qproj + (size_t)bq * Hn;
    qrow[t] = qp[t]; qrow[t + 256] = qp[t + 256];
    __syncthreads();
    if (warp == 0) {
        float s1 = 0.f, s2 = 0.f;
        #pragma unroll
        for (int j = lane; j < Hn; j += 32) { float v = qrow[j]; s1 += v; s2 += v * v; }
        #pragma unroll
        for (int o = 16; o; o >>= 1) {
            s1 += __shfl_xor_sync(0xffffffffu, s1, o);
            s2 += __shfl_xor_sync(0xffffffffu, s2, o);
        }
        if (lane == 0) { sqv[0] = s1; sqv[1] = s2; }
    }
    const float* kpbase = g_kproj + (size_t)b * KLn * Hn;
    for (int r = 0; r < 32; r++) {
        int kk = warp * 32 + r;
        const float* kp = kpbase + (size_t)kk * Hn;
        float sk = 0.f, sk2 = 0.f, d1 = 0.f, d2 = 0.f;
        for (int j = lane; j < Hn; j += 32) {
            float kv = kp[j];
            float p  = kv * qrow[j];
            sk += kv; sk2 += kv * kv; d1 += p; d2 += p * p;
        }
        #pragma unroll
        for (int o = 16; o; o >>= 1) {
            sk  += __shfl_xor_sync(0xffffffffu, sk,  o);
            sk2 += __shfl_xor_sync(0xffffffffu, sk2, o);
            d1  += __shfl_xor_sync(0xffffffffu, d1,  o);
            d2  += __shfl_xor_sync(0xffffffffu, d2,  o);
        }
        if (lane == 0) { s1s[kk] = sk + d1; s2s[kk] = sk2 + d2; }
    }
    __syncthreads();
    {
        float mu = (sqv[0] + s1s[t]) * (1.f / C3n);
        float e2 = (sqv[1] + s2s[t]) * (1.f / C3n);
        g_mu[(size_t)bq * KLn + t] = mu;
        g_rs[(size_t)bq * KLn + t] = rsqrtf(e2 - mu * mu + EPSf);
    }
}

// ---------------- main mma.sync kernel ----------------
// grid (2, 512) = (k-half, bq). 8 warps: hg=warp&3 (32h), kg=warp>>2 (64k).
#define OFF_A   0         // 2 x 32768 (Cu 16K | Cv 16K)
#define OFF_KR  65536     // 2 x 18432 (raw kproj tile, 144B row stride)
#define OFF_BF  102400    // 2 x 16384 (B fragments)
#define OFF_Q   135168    // 2048
#define OFF_HV  137216    // 3584
#define OFF_MU  140800    // 512
#define OFF_RS  141312    // 512
#define OFF_SP  141824    // 2048
#define SM_SZ   143872

__global__ __launch_bounds__(256, 1) void gated_mma(const float* __restrict__ Wo,
                                                    const float* __restrict__ bo,
                                                    float* __restrict__ out) {
    extern __shared__ __align__(16) char sm[];
    const u32 sb = smem_u32(sm);
    const int t = threadIdx.x, lane = t & 31, warp = t >> 5;
    const int hg = warp & 3, kg = warp >> 2;
    const int q = lane >> 2, tid = lane & 3;
    const int kh = blockIdx.x, bq = blockIdx.y, b = bq >> 8;

    float* qrow = (float*)(sm + OFF_Q);
    {
        const float* qp = g_qproj + (size_t)bq * Hn;
        qrow[t] = qp[t]; qrow[t + 256] = qp[t + 256];
    }
    float* muS = (float*)(sm + OFF_MU);
    float* rsS = (float*)(sm + OFF_RS);
    if (t < 128) {
        muS[t] = g_mu[(size_t)bq * KLn + kh * 128 + t];
        rsS[t] = g_rs[(size_t)bq * KLn + kh * 128 + t];
    }

    float accU[2][8][4] = {}, accV[2][8][4] = {};
    float part[8][2] = {};

    const char* kpB = (const char*)(g_kproj + ((size_t)(b * KLn) + kh * 128) * Hn);

    auto stage = [&](int it) {
        const int ht = it >> 4, jc = it & 15, p = it & 1;
        const u32 dA = sb + OFF_A + (u32)p * 32768;
        const u32 dK = sb + OFF_KR + (u32)p * 18432;
        const char* su = (const char*)(g_CuF + (ht * 16 + jc) * 4096);
        const char* sv = (const char*)(g_CvF + (ht * 16 + jc) * 4096);
        #pragma unroll
        for (int i = 0; i < 4; i++) {
            int u = t + i * 256;
            cpasync16(dA + u * 16,         su + u * 16);
            cpasync16(dA + 16384 + u * 16, sv + u * 16);
            int k = u >> 3, cc = u & 7;
            cpasync16(dK + k * 144 + cc * 16, kpB + (size_t)k * 2048 + jc * 128 + cc * 16);
        }
        cp_commit();
    };

    stage(0);
    for (int it = 0; it < 64; it++) {
        if (it < 63) { stage(it + 1); cp_wait1(); }
        else         { cp_wait0(); }
        __syncthreads();

        const int p = it & 1;
        // build B fragments: Ks[j][k] = tf32(kproj[k][j] * q[j])
        {
            const u32 kr = sb + OFF_KR + (u32)p * 18432;
            const u32 bf = sb + OFF_BF + (u32)p * 16384;
            const int jb = (it & 15) * 32;
            #pragma unroll
            for (int nn = 0; nn < 2; nn++) {
                const int ntc = warp * 2 + nn;
                const u32 rowb = kr + (u32)(ntc * 8 + q) * 144;
                #pragma unroll
                for (int kt = 0; kt < 4; kt++) {
                    const int jl = kt * 8 + tid;
                    float v0, v1;
                    asm volatile("ld.shared.f32 %0, [%1];" : "=f"(v0) : "r"(rowb + jl * 4));
                    asm volatile("ld.shared.f32 %0, [%1];" : "=f"(v1) : "r"(rowb + jl * 4 + 16));
                    u32 u0 = tf32r(v0 * qrow[jb + jl]);
                    u32 u1 = tf32r(v1 * qrow[jb + jl + 4]);
                    asm volatile("st.shared.v2.b32 [%0], {%1,%2};"
                                 :: "r"(bf + (u32)(((ntc * 4 + kt) * 32 + lane) * 8)),
                                    "r"(u0), "r"(u1));
                }
            }
        }
        __syncthreads();

        const u32 aU = sb + OFF_A + (u32)p * 32768;
        const u32 aV = aU + 16384;
        const u32 bB = sb + OFF_BF + (u32)p * 16384;

        #pragma unroll
        for (int kt = 0; kt < 4; kt++) {
            u32 au0[4], au1[4], av0[4], av1[4];
            lds128(aU + (u32)(((hg * 2 + 0) * 4 + kt) * 32 + lane) * 16, au0);
            lds128(aU + (u32)(((hg * 2 + 1) * 4 + kt) * 32 + lane) * 16, au1);
            lds128(aV + (u32)(((hg * 2 + 0) * 4 + kt) * 32 + lane) * 16, av0);
            lds128(aV + (u32)(((hg * 2 + 1) * 4 + kt) * 32 + lane) * 16, av1);
            #pragma unroll
            for (int nt = 0; nt < 8; nt++) {
                u32 bfr[2];
                lds64(bB + (u32)((((kg * 8 + nt) * 4 + kt) * 32) + lane) * 8, bfr);
                mma8(accU[0][nt], au0, bfr);
                mma8(accU[1][nt], au1, bfr);
                mma8(accV[0][nt], av0, bfr);
                mma8(accV[1][nt], av1, bfr);
            }
        }

        if ((it & 15) == 15) {
            const int ht = it >> 4;
            __syncthreads();
            float* hv = (float*)(sm + OFF_HV);
            if (t < 128) {
                hv[t]       = g_ruq[(size_t)bq * Hn + ht * 128 + t];
                hv[128 + t] = g_rvq[(size_t)bq * Hn + ht * 128 + t];
                hv[256 + t] = g_gu[ht * 128 + t];
                hv[384 + t] = g_cu[ht * 128 + t];
                hv[512 + t] = g_gv[ht * 128 + t];
                hv[640 + t] = g_cv[ht * 128 + t];
                hv[768 + t] = Wo[ht * 128 + t];
            }
            __syncthreads();
            const float* ruT = g_rukT + ((size_t)b * Hn + ht * 128) * KLn + kh * 128;
            const float* rvT = g_rvkT + ((size_t)b * Hn + ht * 128) * KLn + kh * 128;
            #pragma unroll
            for (int mt = 0; mt < 2; mt++) {
                #pragma unroll
                for (int rr = 0; rr < 2; rr++) {
                    const int hl = (hg * 2 + mt) * 16 + q + rr * 8;
                    const float ruq = hv[hl],       rvq = hv[128 + hl];
                    const float gu  = hv[256 + hl], cu  = hv[384 + hl];
                    const float gv  = hv[512 + hl], cv  = hv[640 + hl];
                    const float wo  = hv[768 + hl];
                    const float* ruB = ruT + (size_t)hl * KLn + kg * 64 + tid * 2;
                    const float* rvB = rvT + (size_t)hl * KLn + kg * 64 + tid * 2;
                    #pragma unroll
                    for (int nt = 0; nt < 8; nt++) {
                        float2 ru2 = *(const float2*)(ruB + nt * 8);
                        float2 rv2 = *(const float2*)(rvB + nt * 8);
                        #pragma unroll
                        for (int e = 0; e < 2; e++) {
                            const int kc = kg * 64 + nt * 8 + tid * 2 + e;
                            const float mu = muS[kc], rs = rsS[kc];
                            const float du = accU[mt][nt][rr * 2 + e];
                            const float dv = accV[mt][nt][rr * 2 + e];
                            const float ruk = e ? ru2.y : ru2.x;
                            const float rvk = e ? rv2.y : rv2.x;
                            float U = rs * (du + ruq + ruk) - mu * rs * gu + cu;
                            float V = rs * (dv + rvq + rvk) - mu * rs * gv + cv;
                            float G = 0.5f * V * (1.0f + erff(V * 0.70710678118654752440f));
                            part[nt][e] += wo * (U * G);
                            accU[mt][nt][rr * 2 + e] = 0.f;
                            accV[mt][nt][rr * 2 + e] = 0.f;
                        }
                    }
                }
            }
        }
        __syncthreads();
    }

    // reduce across q-lanes (same tid), then across hg warps via smem
    #pragma unroll
    for (int nt = 0; nt < 8; nt++)
        #pragma unroll
        for (int e = 0; e < 2; e++) {
            float v = part[nt][e];
            v += __shfl_xor_sync(0xffffffffu, v, 4);
            v += __shfl_xor_sync(0xffffffffu, v, 8);
            v += __shfl_xor_sync(0xffffffffu, v, 16);
            part[nt][e] = v;
        }
    float* sp = (float*)(sm + OFF_SP);
    if (q == 0) {
        #pragma unroll
        for (int nt = 0; nt < 8; nt++)
            #pragma unroll
            for (int e = 0; e < 2; e++)
                sp[hg * 128 + kg * 64 + nt * 8 + tid * 2 + e] = part[nt][e];
    }
    __syncthreads();
    if (t < 128) {
        float r = sp[t] + sp[128 + t] + sp[256 + t] + sp[384 + t] + bo[0];
        out[(size_t)bq * KLn + kh * 128 + t] = r;
    }
}

// ---------------- launch ----------------
extern "C" void kernel_launch(void* const* d_in, const int* in_sizes, int n_in,
                              void* d_out, int out_size) {
    const float* Q   = (const float*)d_in[0];
    const float* K   = (const float*)d_in[1];
    const float* Wq  = (const float*)d_in[2];
    const float* Wk  = (const float*)d_in[3];
    const float* lnw = (const float*)d_in[4];
    const float* lnb = (const float*)d_in[5];
    const float* Wu  = (const float*)d_in[6];
    const float* bu  = (const float*)d_in[7];
    const float* Wv  = (const float*)d_in[8];
    const float* bv  = (const float*)d_in[9];
    const float* Wo  = (const float*)d_in[10];
    const float* bo  = (const float*)d_in[11];
    float* out = (float*)d_out;

    static int smem_set = 0;
    if (!smem_set) {
        cudaFuncSetAttribute(gated_mma, cudaFuncAttributeMaxDynamicSharedMemorySize, SM_SZ);
        smem_set = 1;
    }

    prep_w<<<dim3(512, 1, 5), 256>>>(Wq, Wk, Wu, Wv, lnw, lnb, bu, bv);
    gemm_proj<<<dim3(8, 8, 2), 256>>>(Q, K);
    gemm_hs<<<dim3(8, 64, 7), 256>>>();
    gated_mma<<<dim3(2, 512), 256, SM_SZ>>>(Wo, bo, out);
}

// round 6
// speedup vs baseline: 3.2673x; 1.1971x over previous
#include <cuda_runtime.h>
#include <cstdint>

#define Bb   2
#define QLn  256
#define KLn  256
#define QDn  1024
#define Hn   512
#define C3n  1536
#define EPSf 1e-5f

typedef unsigned long long ull;
typedef unsigned int u32;

// ---------------- device scratch (static, no allocation) ----------------
__device__ __align__(16) float g_WqT[QDn*Hn];
__device__ __align__(16) float g_WkT[QDn*Hn];
__device__ __align__(16) float g_AuT[Hn*Hn];     // [j][h] = Wu[h, j]   * lnw[j]
__device__ __align__(16) float g_AvT[Hn*Hn];
__device__ __align__(16) float g_Bu[Hn*Hn];      // [h][j] = Wu[h, H+j] * lnw[H+j]
__device__ __align__(16) float g_Bv[Hn*Hn];
__device__ __align__(16) u32   g_CuF[262144];    // tf32 A-fragment pack of Cu'
__device__ __align__(16) u32   g_CvF[262144];
__device__ __align__(16) float g_gu[Hn], g_cu[Hn], g_gv[Hn], g_cv[Hn];
__device__ __align__(16) float g_qproj[Bb*QLn*Hn];
__device__ __align__(16) float g_kproj[Bb*KLn*Hn];
__device__ __align__(16) float g_ruq[Bb*QLn*Hn];
__device__ __align__(16) float g_rvq[Bb*QLn*Hn];
__device__ __align__(16) float g_rukT[Bb*Hn*KLn];   // [b][h][k]
__device__ __align__(16) float g_rvkT[Bb*Hn*KLn];
__device__ __align__(16) float g_mu[Bb*QLn*KLn];
__device__ __align__(16) float g_rs[Bb*QLn*KLn];

// ---------------- asm helpers ----------------
__device__ __forceinline__ u32 tf32r(float f) {
    u32 u; asm("cvt.rna.tf32.f32 %0, %1;" : "=r"(u) : "f"(f)); return u;
}
__device__ __forceinline__ u32 smem_u32(const void* p) {
    u32 a;
    asm("{ .reg .u64 t; cvta.to.shared.u64 t, %1; cvt.u32.u64 %0, t; }" : "=r"(a) : "l"(p));
    return a;
}
__device__ __forceinline__ void cpasync16(u32 s, const void* g) {
    asm volatile("cp.async.cg.shared.global [%0], [%1], 16;" :: "r"(s), "l"(g));
}
__device__ __forceinline__ void cp_commit() { asm volatile("cp.async.commit_group;" ::: "memory"); }
__device__ __forceinline__ void lds128(u32 a, u32* r) {
    asm volatile("ld.shared.v4.b32 {%0,%1,%2,%3}, [%4];"
                 : "=r"(r[0]), "=r"(r[1]), "=r"(r[2]), "=r"(r[3]) : "r"(a));
}
// D[m=16 h][n=8 k] += A[16x8 tf32] * B[8x8 tf32]
__device__ __forceinline__ void mma8(float* d, const u32* a, const u32* b) {
    asm volatile(
        "mma.sync.aligned.m16n8k8.row.col.f32.tf32.tf32.f32 "
        "{%0,%1,%2,%3}, {%4,%5,%6,%7}, {%8,%9}, {%0,%1,%2,%3};"
        : "+f"(d[0]), "+f"(d[1]), "+f"(d[2]), "+f"(d[3])
        : "r"(a[0]), "r"(a[1]), "r"(a[2]), "r"(a[3]), "r"(b[0]), "r"(b[1]));
}

// ---------------- merged prep kernel (z: 0 WqT, 1 WkT, 2 split, 3 pack, 4 vec) ----
__global__ __launch_bounds__(256) void prep_w(const float* __restrict__ Wq,
                                              const float* __restrict__ Wk,
                                              const float* __restrict__ Wu,
                                              const float* __restrict__ Wv,
                                              const float* __restrict__ lnw,
                                              const float* __restrict__ lnb,
                                              const float* __restrict__ bu,
                                              const float* __restrict__ bv) {
    __shared__ float T[32][33];
    const int t = threadIdx.x, z = blockIdx.z;
    if (z < 2) {
        const float* W = (z == 0) ? Wq : Wk;
        float* WT = (z == 0) ? g_WqT : g_WkT;
        const int x = t & 31, y8 = t >> 5;
        const int th = (blockIdx.x & 15) * 32;   // h tile
        const int td = (blockIdx.x >> 4) * 32;   // d tile
        #pragma unroll
        for (int r = 0; r < 4; r++) {
            int y = y8 + r * 8;
            T[y][x] = W[(size_t)(th + y) * QDn + td + x];
        }
        __syncthreads();
        #pragma unroll
        for (int r = 0; r < 4; r++) {
            int y = y8 + r * 8;
            WT[(size_t)(td + y) * Hn + th + x] = T[x][y];
        }
    } else if (z == 2) {
        for (int i = blockIdx.x * 256 + t; i < Hn * Hn; i += 512 * 256) {
            int h = i & (Hn - 1), j = i >> 9;
            float w0 = lnw[j];
            g_AuT[i] = Wu[(size_t)h * C3n + j] * w0;
            g_AvT[i] = Wv[(size_t)h * C3n + j] * w0;
        }
        for (int i = blockIdx.x * 256 + t; i < Hn * Hn; i += 512 * 256) {
            int j = i & (Hn - 1), h = i >> 9;
            float w1 = lnw[Hn + j];
            g_Bu[i] = Wu[(size_t)h * C3n + Hn + j] * w1;
            g_Bv[i] = Wv[(size_t)h * C3n + Hn + j] * w1;
        }
    } else if (z == 3) {
        // A-fragment pack: h = ht*128+mtl*16+(lane>>2)+8*(r&1), j = jc*32+kt*8+(lane&3)+4*(r>>1)
        for (int w = blockIdx.x * 256 + t; w < 262144; w += 512 * 256) {
            int r = w & 3, lane = (w >> 2) & 31, kt = (w >> 7) & 3, mtl = (w >> 9) & 7;
            int jc = (w >> 12) & 15, ht = w >> 16;
            int h = ht * 128 + mtl * 16 + (lane >> 2) + 8 * (r & 1);
            int j = jc * 32 + kt * 8 + (lane & 3) + 4 * (r >> 1);
            float wl = lnw[2 * Hn + j];
            g_CuF[w] = tf32r(Wu[(size_t)h * C3n + 2 * Hn + j] * wl);
            g_CvF[w] = tf32r(Wv[(size_t)h * C3n + 2 * Hn + j] * wl);
        }
    } else {
        int gw = blockIdx.x * 8 + (t >> 5);
        int lane = t & 31;
        if (gw >= Hn) return;
        float gu = 0.f, cu = 0.f, gv = 0.f, cv = 0.f;
        for (int c = lane; c < C3n; c += 32) {
            float wl = lnw[c], bl = lnb[c];
            float a = Wu[(size_t)gw * C3n + c], d = Wv[(size_t)gw * C3n + c];
            gu += a * wl; cu += a * bl; gv += d * wl; cv += d * bl;
        }
        #pragma unroll
        for (int o = 16; o; o >>= 1) {
            gu += __shfl_xor_sync(0xffffffffu, gu, o);
            cu += __shfl_xor_sync(0xffffffffu, cu, o);
            gv += __shfl_xor_sync(0xffffffffu, gv, o);
            cv += __shfl_xor_sync(0xffffffffu, cv, o);
        }
        if (lane == 0) {
            g_gu[gw] = gu; g_cu[gw] = cu + bu[gw];
            g_gv[gw] = gv; g_cv[gw] = cv + bv[gw];
        }
    }
}

// ---------------- fp32 GEMM body; NT: C[m][n] = sum_k A[m][k]*B[n][k] ----------------
template<bool NT>
__device__ __forceinline__ void gemm_body(const float* __restrict__ A,
                                          const float* __restrict__ Bm,
                                          float* __restrict__ C,
                                          int N, int Kd, int ldc) {
    __shared__ __align__(16) float As[16][68];
    __shared__ __align__(16) float Bs[16][68];
    const int t  = threadIdx.x;
    const int tx = t & 15, ty = t >> 4;
    const int bm = blockIdx.y * 64, bn = blockIdx.x * 64;
    float acc[4][4] = {};
    for (int kb = 0; kb < Kd; kb += 16) {
        #pragma unroll
        for (int l = 0; l < 4; l++) {
            int e = t + l * 256;
            int m = e >> 4, kk = e & 15;
            As[kk][m] = A[(size_t)(bm + m) * Kd + kb + kk];
            if (NT) {
                Bs[kk][m] = Bm[(size_t)(bn + m) * Kd + kb + kk];
            } else {
                int n = e & 63, k2 = e >> 6;
                Bs[k2][n] = Bm[(size_t)(kb + k2) * N + bn + n];
            }
        }
        __syncthreads();
        #pragma unroll
        for (int kk = 0; kk < 16; kk++) {
            float4 a = *(const float4*)&As[kk][ty * 4];
            float4 b = *(const float4*)&Bs[kk][tx * 4];
            float aw[4] = {a.x, a.y, a.z, a.w};
            float bw[4] = {b.x, b.y, b.z, b.w};
            #pragma unroll
            for (int i = 0; i < 4; i++)
                #pragma unroll
                for (int j = 0; j < 4; j++)
                    acc[i][j] += aw[i] * bw[j];
        }
        __syncthreads();
    }
    #pragma unroll
    for (int i = 0; i < 4; i++) {
        float4 o = make_float4(acc[i][0], acc[i][1], acc[i][2], acc[i][3]);
        *(float4*)&C[(size_t)(bm + ty * 4 + i) * ldc + bn + tx * 4] = o;
    }
}

__global__ __launch_bounds__(256) void gemm_proj(const float* __restrict__ Q,
                                                 const float* __restrict__ K) {
    if (blockIdx.z == 0) gemm_body<false>(Q, g_WqT, g_qproj, Hn, QDn, Hn);
    else                 gemm_body<false>(K, g_WkT, g_kproj, Hn, QDn, Hn);
}

// hidden-term GEMMs + LN stats in one launch. grid (8, 64, 7).
__global__ __launch_bounds__(256) void gemm_hs() {
    const int z = blockIdx.z;
    if (z < 6) {
        if (blockIdx.y >= 8) return;
        switch (z) {
            case 0: gemm_body<false>(g_qproj, g_AuT, g_ruq, Hn, Hn, Hn); return;
            case 1: gemm_body<false>(g_qproj, g_AvT, g_rvq, Hn, Hn, Hn); return;
            default: break;
        }
        if (blockIdx.x >= 4) return;
        const int b = (z - 2) >> 1;
        const float* kp = g_kproj + (size_t)b * KLn * Hn;
        if ((z & 1) == 0) gemm_body<true>(g_Bu, kp, g_rukT + (size_t)b * Hn * KLn, KLn, Hn, KLn);
        else              gemm_body<true>(g_Bv, kp, g_rvkT + (size_t)b * Hn * KLn, KLn, Hn, KLn);
        return;
    }
    // z == 6: LN stats; block handles one bq, all 256 k
    __shared__ __align__(16) float qrow[Hn];
    __shared__ float s1s[KLn], s2s[KLn], sqv[2];
    const int t = threadIdx.x, warp = t >> 5, lane = t & 31;
    const int bq = blockIdx.y * 8 + blockIdx.x;
    const int b = bq >> 8;
    const float* qp = g_qproj + (size_t)bq * Hn;
    qrow[t] = qp[t]; qrow[t + 256] = qp[t + 256];
    __syncthreads();
    if (warp == 0) {
        float s1 = 0.f, s2 = 0.f;
        #pragma unroll
        for (int j = lane; j < Hn; j += 32) { float v = qrow[j]; s1 += v; s2 += v * v; }
        #pragma unroll
        for (int o = 16; o; o >>= 1) {
            s1 += __shfl_xor_sync(0xffffffffu, s1, o);
            s2 += __shfl_xor_sync(0xffffffffu, s2, o);
        }
        if (lane == 0) { sqv[0] = s1; sqv[1] = s2; }
    }
    const float* kpbase = g_kproj + (size_t)b * KLn * Hn;
    for (int r = 0; r < 32; r++) {
        int kk = warp * 32 + r;
        const float* kp = kpbase + (size_t)kk * Hn;
        float sk = 0.f, sk2 = 0.f, d1 = 0.f, d2 = 0.f;
        for (int j = lane; j < Hn; j += 32) {
            float kv = kp[j];
            float p  = kv * qrow[j];
            sk += kv; sk2 += kv * kv; d1 += p; d2 += p * p;
        }
        #pragma unroll
        for (int o = 16; o; o >>= 1) {
            sk  += __shfl_xor_sync(0xffffffffu, sk,  o);
            sk2 += __shfl_xor_sync(0xffffffffu, sk2, o);
            d1  += __shfl_xor_sync(0xffffffffu, d1,  o);
            d2  += __shfl_xor_sync(0xffffffffu, d2,  o);
        }
        if (lane == 0) { s1s[kk] = sk + d1; s2s[kk] = sk2 + d2; }
    }
    __syncthreads();
    {
        float mu = (sqv[0] + s1s[t]) * (1.f / C3n);
        float e2 = (sqv[1] + s2s[t]) * (1.f / C3n);
        g_mu[(size_t)bq * KLn + t] = mu;
        g_rs[(size_t)bq * KLn + t] = rsqrtf(e2 - mu * mu + EPSf);
    }
}

// ---------------- main mma.sync kernel ----------------
// grid (2, 512) = (k-half, bq). 8 warps: hg=warp&3 (32h), kg=warp>>2 (64k).
// Depth-4 cp.async pipeline, ONE barrier/iter; B fragments built in registers.
#define STAGE_SZ 51200   // A (Cu 16K | Cv 16K) + KR 18432 (128 rows x 144B)
#define OFF_STG  0       // 4 stages
#define OFF_Q    204800  // 2048
#define OFF_HV   206848  // 4 ht x 7 arrays x 128 floats = 14336
#define OFF_MU   221184  // 512
#define OFF_RS   221696  // 512
#define OFF_SP   222208  // 2048
#define SM_SZ    224256

__global__ __launch_bounds__(256, 1) void gated_mma(const float* __restrict__ Wo,
                                                    const float* __restrict__ bo,
                                                    float* __restrict__ out) {
    extern __shared__ __align__(16) char sm[];
    const u32 sb = smem_u32(sm);
    const int t = threadIdx.x, lane = t & 31, warp = t >> 5;
    const int hg = warp & 3, kg = warp >> 2;
    const int q = lane >> 2, tid = lane & 3;
    const int kh = blockIdx.x, bq = blockIdx.y, b = bq >> 8;

    float* qrow = (float*)(sm + OFF_Q);
    {
        const float* qp = g_qproj + (size_t)bq * Hn;
        qrow[t] = qp[t]; qrow[t + 256] = qp[t + 256];
    }
    float* muS = (float*)(sm + OFF_MU);
    float* rsS = (float*)(sm + OFF_RS);
    if (t < 128) {
        muS[t] = g_mu[(size_t)bq * KLn + kh * 128 + t];
        rsS[t] = g_rs[(size_t)bq * KLn + kh * 128 + t];
    }
    // preload epilogue constants for all 4 ht chunks
    float* hvA = (float*)(sm + OFF_HV);
    #pragma unroll
    for (int i = t; i < Hn; i += 256) {
        const int ht = i >> 7, hl = i & 127;
        float* hb = hvA + ht * 896;
        hb[hl]       = g_ruq[(size_t)bq * Hn + i];
        hb[128 + hl] = g_rvq[(size_t)bq * Hn + i];
        hb[256 + hl] = g_gu[i];
        hb[384 + hl] = g_cu[i];
        hb[512 + hl] = g_gv[i];
        hb[640 + hl] = g_cv[i];
        hb[768 + hl] = Wo[i];
    }

    float accU[2][8][4] = {}, accV[2][8][4] = {};
    float part[8][2] = {};

    const char* kpB = (const char*)(g_kproj + ((size_t)(b * KLn) + kh * 128) * Hn);

    auto stage = [&](int s) {
        const int ht = s >> 4, jc = s & 15;
        const u32 base = sb + OFF_STG + (u32)(s & 3) * STAGE_SZ;
        const u32 dK = base + 32768;
        const char* su = (const char*)(g_CuF + (ht * 16 + jc) * 4096);
        const char* sv = (const char*)(g_CvF + (ht * 16 + jc) * 4096);
        #pragma unroll
        for (int i = 0; i < 4; i++) {
            int u = t + i * 256;
            cpasync16(base + u * 16,         su + u * 16);
            cpasync16(base + 16384 + u * 16, sv + u * 16);
            int k = u >> 3, cc = u & 7;
            cpasync16(dK + k * 144 + cc * 16, kpB + (size_t)k * 2048 + jc * 128 + cc * 16);
        }
        cp_commit();
    };

    stage(0); stage(1); stage(2);

    // per-lane base into the raw-K tile for the register B build
    const u32 krOff = (u32)((kg * 64 + (lane >> 2)) * 144 + (lane & 3) * 4);

    for (int it = 0; it < 64; it++) {
        if (it <= 60) { stage(it + 3); asm volatile("cp.async.wait_group 3;" ::: "memory"); }
        else if (it == 61) asm volatile("cp.async.wait_group 2;" ::: "memory");
        else if (it == 62) asm volatile("cp.async.wait_group 1;" ::: "memory");
        else               asm volatile("cp.async.wait_group 0;" ::: "memory");
        __syncthreads();

        const u32 base = sb + OFF_STG + (u32)(it & 3) * STAGE_SZ;
        const u32 aU = base, aV = base + 16384;
        const u32 krb = base + 32768 + krOff;
        const int jb = (it & 15) * 32;

        #pragma unroll
        for (int kt = 0; kt < 4; kt++) {
            const float q0 = qrow[jb + kt * 8 + tid];
            const float q1 = qrow[jb + kt * 8 + tid + 4];
            u32 bfr[8][2];
            #pragma unroll
            for (int nt = 0; nt < 8; nt++) {
                float v0, v1;
                const u32 a = krb + (u32)(kt * 32 + nt * 1152);
                asm volatile("ld.shared.f32 %0, [%1];" : "=f"(v0) : "r"(a));
                asm volatile("ld.shared.f32 %0, [%1];" : "=f"(v1) : "r"(a + 16));
                bfr[nt][0] = __float_as_uint(v0 * q0) + 0x1000u;   // == cvt.rna.tf32
                bfr[nt][1] = __float_as_uint(v1 * q1) + 0x1000u;
            }
            u32 au0[4], au1[4], av0[4], av1[4];
            lds128(aU + (u32)(((hg * 2 + 0) * 4 + kt) * 32 + lane) * 16, au0);
            lds128(aU + (u32)(((hg * 2 + 1) * 4 + kt) * 32 + lane) * 16, au1);
            lds128(aV + (u32)(((hg * 2 + 0) * 4 + kt) * 32 + lane) * 16, av0);
            lds128(aV + (u32)(((hg * 2 + 1) * 4 + kt) * 32 + lane) * 16, av1);
            #pragma unroll
            for (int nt = 0; nt < 8; nt++) {
                mma8(accU[0][nt], au0, bfr[nt]);
                mma8(accU[1][nt], au1, bfr[nt]);
                mma8(accV[0][nt], av0, bfr[nt]);
                mma8(accV[1][nt], av1, bfr[nt]);
            }
        }

        if ((it & 15) == 15) {
            const int ht = it >> 4;
            const float* hv = hvA + ht * 896;
            const float* ruT = g_rukT + ((size_t)b * Hn + ht * 128) * KLn + kh * 128;
            const float* rvT = g_rvkT + ((size_t)b * Hn + ht * 128) * KLn + kh * 128;
            #pragma unroll
            for (int mt = 0; mt < 2; mt++) {
                #pragma unroll
                for (int rr = 0; rr < 2; rr++) {
                    const int hl = (hg * 2 + mt) * 16 + q + rr * 8;
                    const float ruq = hv[hl],       rvq = hv[128 + hl];
                    const float gu  = hv[256 + hl], cu  = hv[384 + hl];
                    const float gv  = hv[512 + hl], cv  = hv[640 + hl];
                    const float wo  = hv[768 + hl];
                    const float* ruB = ruT + (size_t)hl * KLn + kg * 64 + tid * 2;
                    const float* rvB = rvT + (size_t)hl * KLn + kg * 64 + tid * 2;
                    #pragma unroll
                    for (int nt = 0; nt < 8; nt++) {
                        float2 ru2 = *(const float2*)(ruB + nt * 8);
                        float2 rv2 = *(const float2*)(rvB + nt * 8);
                        #pragma unroll
                        for (int e = 0; e < 2; e++) {
                            const int kc = kg * 64 + nt * 8 + tid * 2 + e;
                            const float mu = muS[kc], rs = rsS[kc];
                            const float du = accU[mt][nt][rr * 2 + e];
                            const float dv = accV[mt][nt][rr * 2 + e];
                            const float ruk = e ? ru2.y : ru2.x;
                            const float rvk = e ? rv2.y : rv2.x;
                            float U = rs * (du + ruq + ruk) - mu * rs * gu + cu;
                            float V = rs * (dv + rvq + rvk) - mu * rs * gv + cv;
                            float G = 0.5f * V * (1.0f + erff(V * 0.70710678118654752440f));
                            part[nt][e] += wo * (U * G);
                            accU[mt][nt][rr * 2 + e] = 0.f;
                            accV[mt][nt][rr * 2 + e] = 0.f;
                        }
                    }
                }
            }
        }
    }

    // reduce across q-lanes (same tid), then across hg warps via smem
    #pragma unroll
    for (int nt = 0; nt < 8; nt++)
        #pragma unroll
        for (int e = 0; e < 2; e++) {
            float v = part[nt][e];
            v += __shfl_xor_sync(0xffffffffu, v, 4);
            v += __shfl_xor_sync(0xffffffffu, v, 8);
            v += __shfl_xor_sync(0xffffffffu, v, 16);
            part[nt][e] = v;
        }
    float* sp = (float*)(sm + OFF_SP);
    __syncthreads();
    if (q == 0) {
        #pragma unroll
        for (int nt = 0; nt < 8; nt++)
            #pragma unroll
            for (int e = 0; e < 2; e++)
                sp[hg * 128 + kg * 64 + nt * 8 + tid * 2 + e] = part[nt][e];
    }
    __syncthreads();
    if (t < 128) {
        float r = sp[t] + sp[128 + t] + sp[256 + t] + sp[384 + t] + bo[0];
        out[(size_t)bq * KLn + kh * 128 + t] = r;
    }
}

// ---------------- launch ----------------
extern "C" void kernel_launch(void* const* d_in, const int* in_sizes, int n_in,
                              void* d_out, int out_size) {
    const float* Q   = (const float*)d_in[0];
    const float* K   = (const float*)d_in[1];
    const float* Wq  = (const float*)d_in[2];
    const float* Wk  = (const float*)d_in[3];
    const float* lnw = (const float*)d_in[4];
    const float* lnb = (const float*)d_in[5];
    const float* Wu  = (const float*)d_in[6];
    const float* bu  = (const float*)d_in[7];
    const float* Wv  = (const float*)d_in[8];
    const float* bv  = (const float*)d_in[9];
    const float* Wo  = (const float*)d_in[10];
    const float* bo  = (const float*)d_in[11];
    float* out = (float*)d_out;

    static int smem_set = 0;
    if (!smem_set) {
        cudaFuncSetAttribute(gated_mma, cudaFuncAttributeMaxDynamicSharedMemorySize, SM_SZ);
        smem_set = 1;
    }

    prep_w<<<dim3(512, 1, 5), 256>>>(Wq, Wk, Wu, Wv, lnw, lnb, bu, bv);
    gemm_proj<<<dim3(8, 8, 2), 256>>>(Q, K);
    gemm_hs<<<dim3(8, 64, 7), 256>>>();
    gated_mma<<<dim3(2, 512), 256, SM_SZ>>>(Wo, bo, out);
}

// round 7
// speedup vs baseline: 3.3976x; 1.0399x over previous
#include <cuda_runtime.h>
#include <cstdint>

#define Bb   2
#define QLn  256
#define KLn  256
#define QDn  1024
#define Hn   512
#define C3n  1536
#define EPSf 1e-5f

typedef unsigned long long ull;
typedef unsigned int u32;

// ---------------- device scratch (static, no allocation) ----------------
__device__ __align__(16) float g_WqT[QDn*Hn];
__device__ __align__(16) float g_WkT[QDn*Hn];
__device__ __align__(16) float g_AuT[Hn*Hn];     // [j][h] = Wu[h, j]   * lnw[j]
__device__ __align__(16) float g_AvT[Hn*Hn];
__device__ __align__(16) float g_Bu[Hn*Hn];      // [h][j] = Wu[h, H+j] * lnw[H+j]
__device__ __align__(16) float g_Bv[Hn*Hn];
__device__ __align__(16) u32   g_CuF[262144];    // tf32 A-fragment pack of Cu'
__device__ __align__(16) u32   g_CvF[262144];
__device__ __align__(16) float g_gu[Hn], g_cu[Hn], g_gv[Hn], g_cv[Hn];
__device__ __align__(16) float g_qproj[Bb*QLn*Hn];
__device__ __align__(16) float g_kproj[Bb*KLn*Hn];
__device__ __align__(16) float g_ruq[Bb*QLn*Hn];
__device__ __align__(16) float g_rvq[Bb*QLn*Hn];
__device__ __align__(16) float g_rukT[Bb*Hn*KLn];   // [b][h][k]
__device__ __align__(16) float g_rvkT[Bb*Hn*KLn];
__device__ __align__(16) float g_mu[Bb*QLn*KLn];
__device__ __align__(16) float g_rs[Bb*QLn*KLn];

// ---------------- asm helpers ----------------
__device__ __forceinline__ u32 tf32r(float f) {
    u32 u; asm("cvt.rna.tf32.f32 %0, %1;" : "=r"(u) : "f"(f)); return u;
}
__device__ __forceinline__ u32 smem_u32(const void* p) {
    u32 a;
    asm("{ .reg .u64 t; cvta.to.shared.u64 t, %1; cvt.u32.u64 %0, t; }" : "=r"(a) : "l"(p));
    return a;
}
__device__ __forceinline__ void cpasync16(u32 s, const void* g) {
    asm volatile("cp.async.cg.shared.global [%0], [%1], 16;" :: "r"(s), "l"(g));
}
__device__ __forceinline__ void cp_commit() { asm volatile("cp.async.commit_group;" ::: "memory"); }
__device__ __forceinline__ void lds128(u32 a, u32* r) {
    asm volatile("ld.shared.v4.b32 {%0,%1,%2,%3}, [%4];"
                 : "=r"(r[0]), "=r"(r[1]), "=r"(r[2]), "=r"(r[3]) : "r"(a));
}
// D[m=16 h][n=8 k] += A[16x8 tf32] * B[8x8 tf32]
__device__ __forceinline__ void mma8(float* d, const u32* a, const u32* b) {
    asm volatile(
        "mma.sync.aligned.m16n8k8.row.col.f32.tf32.tf32.f32 "
        "{%0,%1,%2,%3}, {%4,%5,%6,%7}, {%8,%9}, {%0,%1,%2,%3};"
        : "+f"(d[0]), "+f"(d[1]), "+f"(d[2]), "+f"(d[3])
        : "r"(a[0]), "r"(a[1]), "r"(a[2]), "r"(a[3]), "r"(b[0]), "r"(b[1]));
}

// ---------------- merged prep kernel (z: 0 WqT, 1 WkT, 2 split, 3 pack, 4 vec) ----
__global__ __launch_bounds__(256) void prep_w(const float* __restrict__ Wq,
                                              const float* __restrict__ Wk,
                                              const float* __restrict__ Wu,
                                              const float* __restrict__ Wv,
                                              const float* __restrict__ lnw,
                                              const float* __restrict__ lnb,
                                              const float* __restrict__ bu,
                                              const float* __restrict__ bv) {
    __shared__ float T[32][33];
    const int t = threadIdx.x, z = blockIdx.z;
    if (z < 2) {
        const float* W = (z == 0) ? Wq : Wk;
        float* WT = (z == 0) ? g_WqT : g_WkT;
        const int x = t & 31, y8 = t >> 5;
        const int th = (blockIdx.x & 15) * 32;   // h tile
        const int td = (blockIdx.x >> 4) * 32;   // d tile
        #pragma unroll
        for (int r = 0; r < 4; r++) {
            int y = y8 + r * 8;
            T[y][x] = W[(size_t)(th + y) * QDn + td + x];
        }
        __syncthreads();
        #pragma unroll
        for (int r = 0; r < 4; r++) {
            int y = y8 + r * 8;
            WT[(size_t)(td + y) * Hn + th + x] = T[x][y];
        }
    } else if (z == 2) {
        for (int i = blockIdx.x * 256 + t; i < Hn * Hn; i += 512 * 256) {
            int h = i & (Hn - 1), j = i >> 9;
            float w0 = lnw[j];
            g_AuT[i] = Wu[(size_t)h * C3n + j] * w0;
            g_AvT[i] = Wv[(size_t)h * C3n + j] * w0;
        }
        for (int i = blockIdx.x * 256 + t; i < Hn * Hn; i += 512 * 256) {
            int j = i & (Hn - 1), h = i >> 9;
            float w1 = lnw[Hn + j];
            g_Bu[i] = Wu[(size_t)h * C3n + Hn + j] * w1;
            g_Bv[i] = Wv[(size_t)h * C3n + Hn + j] * w1;
        }
    } else if (z == 3) {
        // A-fragment pack: h = ht*128+mtl*16+(lane>>2)+8*(r&1), j = jc*32+kt*8+(lane&3)+4*(r>>1)
        for (int w = blockIdx.x * 256 + t; w < 262144; w += 512 * 256) {
            int r = w & 3, lane = (w >> 2) & 31, kt = (w >> 7) & 3, mtl = (w >> 9) & 7;
            int jc = (w >> 12) & 15, ht = w >> 16;
            int h = ht * 128 + mtl * 16 + (lane >> 2) + 8 * (r & 1);
            int j = jc * 32 + kt * 8 + (lane & 3) + 4 * (r >> 1);
            float wl = lnw[2 * Hn + j];
            g_CuF[w] = tf32r(Wu[(size_t)h * C3n + 2 * Hn + j] * wl);
            g_CvF[w] = tf32r(Wv[(size_t)h * C3n + 2 * Hn + j] * wl);
        }
    } else {
        int gw = blockIdx.x * 8 + (t >> 5);
        int lane = t & 31;
        if (gw >= Hn) return;
        float gu = 0.f, cu = 0.f, gv = 0.f, cv = 0.f;
        for (int c = lane; c < C3n; c += 32) {
            float wl = lnw[c], bl = lnb[c];
            float a = Wu[(size_t)gw * C3n + c], d = Wv[(size_t)gw * C3n + c];
            gu += a * wl; cu += a * bl; gv += d * wl; cv += d * bl;
        }
        #pragma unroll
        for (int o = 16; o; o >>= 1) {
            gu += __shfl_xor_sync(0xffffffffu, gu, o);
            cu += __shfl_xor_sync(0xffffffffu, cu, o);
            gv += __shfl_xor_sync(0xffffffffu, gv, o);
            cv += __shfl_xor_sync(0xffffffffu, cv, o);
        }
        if (lane == 0) {
            g_gu[gw] = gu; g_cu[gw] = cu + bu[gw];
            g_gv[gw] = gv; g_cv[gw] = cv + bv[gw];
        }
    }
}

// ---------------- fp32 GEMM body; NT: C[m][n] = sum_k A[m][k]*B[n][k] ----------------
template<bool NT>
__device__ __forceinline__ void gemm_body(const float* __restrict__ A,
                                          const float* __restrict__ Bm,
                                          float* __restrict__ C,
                                          int N, int Kd, int ldc) {
    __shared__ __align__(16) float As[16][68];
    __shared__ __align__(16) float Bs[16][68];
    const int t  = threadIdx.x;
    const int tx = t & 15, ty = t >> 4;
    const int bm = blockIdx.y * 64, bn = blockIdx.x * 64;
    float acc[4][4] = {};
    for (int kb = 0; kb < Kd; kb += 16) {
        #pragma unroll
        for (int l = 0; l < 4; l++) {
            int e = t + l * 256;
            int m = e >> 4, kk = e & 15;
            As[kk][m] = A[(size_t)(bm + m) * Kd + kb + kk];
            if (NT) {
                Bs[kk][m] = Bm[(size_t)(bn + m) * Kd + kb + kk];
            } else {
                int n = e & 63, k2 = e >> 6;
                Bs[k2][n] = Bm[(size_t)(kb + k2) * N + bn + n];
            }
        }
        __syncthreads();
        #pragma unroll
        for (int kk = 0; kk < 16; kk++) {
            float4 a = *(const float4*)&As[kk][ty * 4];
            float4 b = *(const float4*)&Bs[kk][tx * 4];
            float aw[4] = {a.x, a.y, a.z, a.w};
            float bw[4] = {b.x, b.y, b.z, b.w};
            #pragma unroll
            for (int i = 0; i < 4; i++)
                #pragma unroll
                for (int j = 0; j < 4; j++)
                    acc[i][j] += aw[i] * bw[j];
        }
        __syncthreads();
    }
    #pragma unroll
    for (int i = 0; i < 4; i++) {
        float4 o = make_float4(acc[i][0], acc[i][1], acc[i][2], acc[i][3]);
        *(float4*)&C[(size_t)(bm + ty * 4 + i) * ldc + bn + tx * 4] = o;
    }
}

__global__ __launch_bounds__(256) void gemm_proj(const float* __restrict__ Q,
                                                 const float* __restrict__ K) {
    if (blockIdx.z == 0) gemm_body<false>(Q, g_WqT, g_qproj, Hn, QDn, Hn);
    else                 gemm_body<false>(K, g_WkT, g_kproj, Hn, QDn, Hn);
}

// hidden-term GEMMs + LN stats in one launch. grid (8, 64, 7).
__global__ __launch_bounds__(256) void gemm_hs() {
    const int z = blockIdx.z;
    if (z < 6) {
        if (blockIdx.y >= 8) return;
        switch (z) {
            case 0: gemm_body<false>(g_qproj, g_AuT, g_ruq, Hn, Hn, Hn); return;
            case 1: gemm_body<false>(g_qproj, g_AvT, g_rvq, Hn, Hn, Hn); return;
            default: break;
        }
        if (blockIdx.x >= 4) return;
        const int b = (z - 2) >> 1;
        const float* kp = g_kproj + (size_t)b * KLn * Hn;
        if ((z & 1) == 0) gemm_body<true>(g_Bu, kp, g_rukT + (size_t)b * Hn * KLn, KLn, Hn, KLn);
        else              gemm_body<true>(g_Bv, kp, g_rvkT + (size_t)b * Hn * KLn, KLn, Hn, KLn);
        return;
    }
    // z == 6: LN stats; block handles one bq, all 256 k
    __shared__ __align__(16) float qrow[Hn];
    __shared__ float s1s[KLn], s2s[KLn], sqv[2];
    const int t = threadIdx.x, warp = t >> 5, lane = t & 31;
    const int bq = blockIdx.y * 8 + blockIdx.x;
    const int b = bq >> 8;
    const float* qp = g_qproj + (size_t)bq * Hn;
    qrow[t] = qp[t]; qrow[t + 256] = qp[t + 256];
    __syncthreads();
    if (warp == 0) {
        float s1 = 0.f, s2 = 0.f;
        #pragma unroll
        for (int j = lane; j < Hn; j += 32) { float v = qrow[j]; s1 += v; s2 += v * v; }
        #pragma unroll
        for (int o = 16; o; o >>= 1) {
            s1 += __shfl_xor_sync(0xffffffffu, s1, o);
            s2 += __shfl_xor_sync(0xffffffffu, s2, o);
        }
        if (lane == 0) { sqv[0] = s1; sqv[1] = s2; }
    }
    const float* kpbase = g_kproj + (size_t)b * KLn * Hn;
    for (int r = 0; r < 32; r++) {
        int kk = warp * 32 + r;
        const float* kp = kpbase + (size_t)kk * Hn;
        float sk = 0.f, sk2 = 0.f, d1 = 0.f, d2 = 0.f;
        for (int j = lane; j < Hn; j += 32) {
            float kv = kp[j];
            float p  = kv * qrow[j];
            sk += kv; sk2 += kv * kv; d1 += p; d2 += p * p;
        }
        #pragma unroll
        for (int o = 16; o; o >>= 1) {
            sk  += __shfl_xor_sync(0xffffffffu, sk,  o);
            sk2 += __shfl_xor_sync(0xffffffffu, sk2, o);
            d1  += __shfl_xor_sync(0xffffffffu, d1,  o);
            d2  += __shfl_xor_sync(0xffffffffu, d2,  o);
        }
        if (lane == 0) { s1s[kk] = sk + d1; s2s[kk] = sk2 + d2; }
    }
    __syncthreads();
    {
        float mu = (sqv[0] + s1s[t]) * (1.f / C3n);
        float e2 = (sqv[1] + s2s[t]) * (1.f / C3n);
        g_mu[(size_t)bq * KLn + t] = mu;
        g_rs[(size_t)bq * KLn + t] = rsqrtf(e2 - mu * mu + EPSf);
    }
}

// ---------------- main mma.sync kernel ----------------
// grid (2, 512) = (k-half, bq). 8 warps: hg=warp&1 (64h), kg=warp>>1 (32k).
// 64-j chunks, depth-2 cp.async pipeline, ONE barrier/iter, reg-built B frags.
#define STAGE_SZ 100352  // Cu 32768 | Cv 32768 | KR 34816 (128 rows x 272B)
#define OFF_STG  0       // 2 stages
#define OFF_Q    200704  // 2048
#define OFF_HV   202752  // 4 ht x 7 arrays x 128 floats = 14336
#define OFF_MU   217088  // 512 (holds mu*rs)
#define OFF_RS   217600  // 512
#define OFF_SP   218112  // 1024
#define SM_SZ    219136

__global__ __launch_bounds__(256, 1) void gated_mma(const float* __restrict__ Wo,
                                                    const float* __restrict__ bo,
                                                    float* __restrict__ out) {
    extern __shared__ __align__(16) char sm[];
    const u32 sb = smem_u32(sm);
    const int t = threadIdx.x, lane = t & 31, warp = t >> 5;
    const int hg = warp & 1, kg = warp >> 1;
    const int q = lane >> 2, tid = lane & 3;
    const int kh = blockIdx.x, bq = blockIdx.y, b = bq >> 8;

    float* qrow = (float*)(sm + OFF_Q);
    {
        const float* qp = g_qproj + (size_t)bq * Hn;
        qrow[t] = qp[t]; qrow[t + 256] = qp[t + 256];
    }
    float* muS = (float*)(sm + OFF_MU);
    float* rsS = (float*)(sm + OFF_RS);
    if (t < 128) {
        float rs = g_rs[(size_t)bq * KLn + kh * 128 + t];
        rsS[t] = rs;
        muS[t] = g_mu[(size_t)bq * KLn + kh * 128 + t] * rs;   // mu*rs
    }
    // preload epilogue constants for all 4 ht chunks
    float* hvA = (float*)(sm + OFF_HV);
    #pragma unroll
    for (int i = t; i < Hn; i += 256) {
        const int ht = i >> 7, hl = i & 127;
        float* hb = hvA + ht * 896;
        hb[hl]       = g_ruq[(size_t)bq * Hn + i];
        hb[128 + hl] = g_rvq[(size_t)bq * Hn + i];
        hb[256 + hl] = g_gu[i];
        hb[384 + hl] = g_cu[i];
        hb[512 + hl] = g_gv[i];
        hb[640 + hl] = g_cv[i];
        hb[768 + hl] = Wo[i];
    }

    float accU[4][4][4] = {}, accV[4][4][4] = {};
    float part[4][2] = {};

    const char* kpB = (const char*)(g_kproj + ((size_t)(b * KLn) + kh * 128) * Hn);

    auto stage = [&](int s) {
        const int ht = s >> 3, jc2 = s & 7;
        const u32 base = sb + OFF_STG + (u32)(s & 1) * STAGE_SZ;
        const u32 dK = base + 65536;
        const char* su = (const char*)(g_CuF + (ht * 16 + jc2 * 2) * 4096);
        const char* sv = (const char*)(g_CvF + (ht * 16 + jc2 * 2) * 4096);
        #pragma unroll
        for (int i = 0; i < 8; i++) {
            int u = t + i * 256;
            cpasync16(base + u * 16,         su + u * 16);
            cpasync16(base + 32768 + u * 16, sv + u * 16);
            int k = u >> 4, cc = u & 15;
            cpasync16(dK + k * 272 + cc * 16, kpB + (size_t)k * 2048 + jc2 * 256 + cc * 16);
        }
        cp_commit();
    };

    stage(0);

    // per-lane base into the raw-K tile for the register B build
    const u32 krOff = (u32)((kg * 32 + q) * 272 + tid * 4);

    for (int it = 0; it < 32; it++) {
        if (it < 31) { stage(it + 1); asm volatile("cp.async.wait_group 1;" ::: "memory"); }
        else         { asm volatile("cp.async.wait_group 0;" ::: "memory"); }
        __syncthreads();

        const u32 base = sb + OFF_STG + (u32)(it & 1) * STAGE_SZ;
        const u32 aU = base, aV = base + 32768;
        const u32 krb = base + 65536 + krOff;
        const int jb = (it & 7) * 64;

        #pragma unroll
        for (int kt = 0; kt < 8; kt++) {
            const int jcl = kt >> 2, ktl = kt & 3;
            const float q0 = qrow[jb + kt * 8 + tid];
            const float q1 = qrow[jb + kt * 8 + tid + 4];
            u32 bfr[4][2];
            #pragma unroll
            for (int nt = 0; nt < 4; nt++) {
                float v0, v1;
                const u32 a = krb + (u32)(kt * 32 + nt * 2176);
                asm volatile("ld.shared.f32 %0, [%1];" : "=f"(v0) : "r"(a));
                asm volatile("ld.shared.f32 %0, [%1];" : "=f"(v1) : "r"(a + 16));
                bfr[nt][0] = __float_as_uint(v0 * q0) + 0x1000u;   // == cvt.rna.tf32
                bfr[nt][1] = __float_as_uint(v1 * q1) + 0x1000u;
            }
            u32 au[4][4], av[4][4];
            #pragma unroll
            for (int mt = 0; mt < 4; mt++) {
                const u32 fo = (u32)jcl * 16384 +
                               (u32)((((hg * 4 + mt) * 4 + ktl) * 32 + lane) * 16);
                lds128(aU + fo, au[mt]);
                lds128(aV + fo, av[mt]);
            }
            #pragma unroll
            for (int mt = 0; mt < 4; mt++)
                #pragma unroll
                for (int nt = 0; nt < 4; nt++) {
                    mma8(accU[mt][nt], au[mt], bfr[nt]);
                    mma8(accV[mt][nt], av[mt], bfr[nt]);
                }
        }

        if ((it & 7) == 7) {
            const int ht = it >> 3;
            const float* hv = hvA + ht * 896;
            const float* ruT = g_rukT + ((size_t)b * Hn + ht * 128) * KLn + kh * 128;
            const float* rvT = g_rvkT + ((size_t)b * Hn + ht * 128) * KLn + kh * 128;
            #pragma unroll
            for (int mt = 0; mt < 4; mt++) {
                #pragma unroll
                for (int rr = 0; rr < 2; rr++) {
                    const int hl = (hg * 4 + mt) * 16 + q + rr * 8;
                    const float ruq = hv[hl],       rvq = hv[128 + hl];
                    const float gu  = hv[256 + hl], cu  = hv[384 + hl];
                    const float gv  = hv[512 + hl], cv  = hv[640 + hl];
                    const float wo  = hv[768 + hl];
                    const float* ruB = ruT + (size_t)hl * KLn + kg * 32 + tid * 2;
                    const float* rvB = rvT + (size_t)hl * KLn + kg * 32 + tid * 2;
                    #pragma unroll
                    for (int nt = 0; nt < 4; nt++) {
                        float2 ru2 = *(const float2*)(ruB + nt * 8);
                        float2 rv2 = *(const float2*)(rvB + nt * 8);
                        #pragma unroll
                        for (int e = 0; e < 2; e++) {
                            const int kc = kg * 32 + nt * 8 + tid * 2 + e;
                            const float mrs = muS[kc], rs = rsS[kc];
                            const float du = accU[mt][nt][rr * 2 + e];
                            const float dv = accV[mt][nt][rr * 2 + e];
                            const float ruk = e ? ru2.y : ru2.x;
                            const float rvk = e ? rv2.y : rv2.x;
                            float U = rs * (du + ruq + ruk) - mrs * gu + cu;
                            float V = rs * (dv + rvq + rvk) - mrs * gv + cv;
                            float G = 0.5f * V * (1.0f + erff(V * 0.70710678118654752440f));
                            part[nt][e] += wo * (U * G);
                            accU[mt][nt][rr * 2 + e] = 0.f;
                            accV[mt][nt][rr * 2 + e] = 0.f;
                        }
                    }
                }
            }
        }
    }

    // reduce across q-lanes (same tid), then across the 2 hg warps via smem
    #pragma unroll
    for (int nt = 0; nt < 4; nt++)
        #pragma unroll
        for (int e = 0; e < 2; e++) {
            float v = part[nt][e];
            v += __shfl_xor_sync(0xffffffffu, v, 4);
            v += __shfl_xor_sync(0xffffffffu, v, 8);
            v += __shfl_xor_sync(0xffffffffu, v, 16);
            part[nt][e] = v;
        }
    float* sp = (float*)(sm + OFF_SP);
    __syncthreads();
    if (q == 0) {
        #pragma unroll
        for (int nt = 0; nt < 4; nt++)
            #pragma unroll
            for (int e = 0; e < 2; e++)
                sp[hg * 128 + kg * 32 + nt * 8 + tid * 2 + e] = part[nt][e];
    }
    __syncthreads();
    if (t < 128) {
        float r = sp[t] + sp[128 + t] + bo[0];
        out[(size_t)bq * KLn + kh * 128 + t] = r;
    }
}

// ---------------- launch ----------------
extern "C" void kernel_launch(void* const* d_in, const int* in_sizes, int n_in,
                              void* d_out, int out_size) {
    const float* Q   = (const float*)d_in[0];
    const float* K   = (const float*)d_in[1];
    const float* Wq  = (const float*)d_in[2];
    const float* Wk  = (const float*)d_in[3];
    const float* lnw = (const float*)d_in[4];
    const float* lnb = (const float*)d_in[5];
    const float* Wu  = (const float*)d_in[6];
    const float* bu  = (const float*)d_in[7];
    const float* Wv  = (const float*)d_in[8];
    const float* bv  = (const float*)d_in[9];
    const float* Wo  = (const float*)d_in[10];
    const float* bo  = (const float*)d_in[11];
    float* out = (float*)d_out;

    static int smem_set = 0;
    if (!smem_set) {
        cudaFuncSetAttribute(gated_mma, cudaFuncAttributeMaxDynamicSharedMemorySize, SM_SZ);
        smem_set = 1;
    }

    prep_w<<<dim3(512, 1, 5), 256>>>(Wq, Wk, Wu, Wv, lnw, lnb, bu, bv);
    gemm_proj<<<dim3(8, 8, 2), 256>>>(Q, K);
    gemm_hs<<<dim3(8, 64, 7), 256>>>();
    gated_mma<<<dim3(2, 512), 256, SM_SZ>>>(Wo, bo, out);
}